// round 1
// baseline (speedup 1.0000x reference)
#include <cuda_runtime.h>
#include <math.h>

#define BSZ 2
#define SEQ 2048
#define HIDDEN 2048
#define NH 32
#define NKV 8
#define HD 64
#define NREP 4

// Scratch (static device arrays — no allocation).
__device__ float g_q[BSZ * NH * SEQ * HD];      // [b, h, s, d]
__device__ float g_k[BSZ * NKV * SEQ * HD];     // [b, kvh, s, d]
__device__ float g_v[BSZ * NKV * SEQ * HD];     // [b, kvh, s, d]
__device__ float g_attn[BSZ * SEQ * NH * HD];   // [b, s, h*d]

// ---------------------------------------------------------------------------
// SGEMM: C = A[M,K] @ B[K,N], row-major. 128x128 tile, BK=8, 256 thr, 8x8/thr.
// scatter_heads == 0: C[m*N + n]
// scatter_heads  > 0: write to [b, h, s, d] layout (b=m/SEQ, s=m%SEQ, h=n/HD, d=n%HD)
// ---------------------------------------------------------------------------
__global__ __launch_bounds__(256, 2)
void sgemm_kernel(const float* __restrict__ A, const float* __restrict__ B,
                  float* __restrict__ C, int M, int N, int K, int scatter_heads)
{
    __shared__ float As[8][128];   // transposed A tile
    __shared__ float Bs[8][128];

    const int bx = blockIdx.x;   // N tile
    const int by = blockIdx.y;   // M tile
    const int tid = threadIdx.x;
    const int tx = tid & 15;
    const int ty = tid >> 4;

    const float* Ablk = A + (size_t)(by * 128) * K;
    const float* Bblk = B + bx * 128;

    float acc[8][8];
#pragma unroll
    for (int i = 0; i < 8; i++)
#pragma unroll
        for (int j = 0; j < 8; j++) acc[i][j] = 0.0f;

    const int arow = tid >> 1;
    const int acol = (tid & 1) * 4;
    const int brow = tid >> 5;
    const int bcol = (tid & 31) * 4;

    for (int k0 = 0; k0 < K; k0 += 8) {
        float4 av = *(const float4*)(Ablk + (size_t)arow * K + k0 + acol);
        As[acol + 0][arow] = av.x;
        As[acol + 1][arow] = av.y;
        As[acol + 2][arow] = av.z;
        As[acol + 3][arow] = av.w;
        float4 bv = *(const float4*)(Bblk + (size_t)(k0 + brow) * N + bcol);
        *(float4*)&Bs[brow][bcol] = bv;
        __syncthreads();

#pragma unroll
        for (int kk = 0; kk < 8; kk++) {
            float a[8], b[8];
            *(float4*)(a)     = *(const float4*)&As[kk][ty * 8];
            *(float4*)(a + 4) = *(const float4*)&As[kk][ty * 8 + 4];
            *(float4*)(b)     = *(const float4*)&Bs[kk][tx * 8];
            *(float4*)(b + 4) = *(const float4*)&Bs[kk][tx * 8 + 4];
#pragma unroll
            for (int i = 0; i < 8; i++)
#pragma unroll
                for (int j = 0; j < 8; j++)
                    acc[i][j] = fmaf(a[i], b[j], acc[i][j]);
        }
        __syncthreads();
    }

#pragma unroll
    for (int i = 0; i < 8; i++) {
        int m = by * 128 + ty * 8 + i;
        int bb = m / SEQ;
        int ss = m % SEQ;
#pragma unroll
        for (int j = 0; j < 8; j++) {
            int n = bx * 128 + tx * 8 + j;
            if (scatter_heads > 0) {
                int h = n / HD, d = n % HD;
                C[(((size_t)bb * scatter_heads + h) * SEQ + ss) * HD + d] = acc[i][j];
            } else {
                C[(size_t)m * N + n] = acc[i][j];
            }
        }
    }
}

// ---------------------------------------------------------------------------
// RoPE (in-place), replicating the reference's fp32 math path.
// x layout: [total_bh, SEQ, HD]; one thread per (bh, s, pair p in 0..31).
// ---------------------------------------------------------------------------
__global__ void rope_kernel(float* __restrict__ x, int total_bh)
{
    int idx = blockIdx.x * blockDim.x + threadIdx.x;
    int total = total_bh * SEQ * 32;
    if (idx >= total) return;
    int p = idx & 31;
    int s = (idx >> 5) & (SEQ - 1);
    int bh = idx / (SEQ * 32);

    float* base = x + ((size_t)bh * SEQ + s) * HD;
    float inv = powf(10000.0f, -((float)(2 * p) / 64.0f));
    float ang = (float)s * inv;
    float c, si;
    sincosf(ang, &si, &c);
    float x1 = base[p];
    float x2 = base[p + 32];
    base[p]      = x1 * c - x2 * si;
    base[p + 32] = x2 * c + x1 * si;
}

// ---------------------------------------------------------------------------
// Flash attention (fp32, causal). 64x64 tiles, 256 threads, 4x4 per thread.
// Q/K/V: [b, (kv)h, s, d]. Output: [b, s, h*HD] for the final GEMM.
// ---------------------------------------------------------------------------
__global__ __launch_bounds__(256, 2)
void flash_kernel(const float* __restrict__ Q, const float* __restrict__ K,
                  const float* __restrict__ V, float* __restrict__ O)
{
    extern __shared__ float sm[];
    float* Qs = sm;                 // [64][64]
    float* Ks = Qs + 64 * 64;       // [64][65] (padded: rows = k columns)
    float* Vs = Ks + 64 * 65;       // [64][64] (rows = k index, cols = d)
    float* Ps = Vs + 64 * 64;       // [64][64]

    const int qb = blockIdx.x;      // query tile (0..31)
    const int h  = blockIdx.y;
    const int b  = blockIdx.z;
    const int tid = threadIdx.x;
    const int tx = tid & 15;
    const int ty = tid >> 4;

    const float* Qg = Q + (((size_t)b * NH + h) * SEQ + qb * 64) * HD;
    const float* Kg = K + ((size_t)b * NKV + h / NREP) * SEQ * HD;
    const float* Vg = V + ((size_t)b * NKV + h / NREP) * SEQ * HD;

    // Load Q tile (64x64 floats, float4).
#pragma unroll
    for (int i = 0; i < 4; i++) {
        int f = tid + 256 * i;          // float4 index 0..1023
        int r = f >> 4;
        int c4 = (f & 15) << 2;
        *(float4*)&Qs[r * 64 + c4] = *(const float4*)&Qg[r * HD + c4];
    }

    float m_i[4], l_i[4], o_acc[4][4];
#pragma unroll
    for (int i = 0; i < 4; i++) {
        m_i[i] = -INFINITY;
        l_i[i] = 0.0f;
#pragma unroll
        for (int j = 0; j < 4; j++) o_acc[i][j] = 0.0f;
    }

    const int nkt = qb + 1;             // causal: only tiles up to diagonal
    for (int kt = 0; kt < nkt; kt++) {
        // Load K (padded, scalar stores) and V (float4) tiles.
#pragma unroll
        for (int i = 0; i < 4; i++) {
            int f = tid + 256 * i;
            int r = f >> 4;
            int c4 = (f & 15) << 2;
            float4 kv = *(const float4*)&Kg[((size_t)kt * 64 + r) * HD + c4];
            Ks[r * 65 + c4 + 0] = kv.x;
            Ks[r * 65 + c4 + 1] = kv.y;
            Ks[r * 65 + c4 + 2] = kv.z;
            Ks[r * 65 + c4 + 3] = kv.w;
            *(float4*)&Vs[r * 64 + c4] =
                *(const float4*)&Vg[((size_t)kt * 64 + r) * HD + c4];
        }
        __syncthreads();

        // S = Q @ K^T (4x4 per thread)
        float s_acc[4][4];
#pragma unroll
        for (int i = 0; i < 4; i++)
#pragma unroll
            for (int j = 0; j < 4; j++) s_acc[i][j] = 0.0f;

        for (int dd = 0; dd < 64; dd++) {
            float a[4], bb[4];
#pragma unroll
            for (int i = 0; i < 4; i++) a[i] = Qs[(ty * 4 + i) * 64 + dd];
#pragma unroll
            for (int j = 0; j < 4; j++) bb[j] = Ks[(tx * 4 + j) * 65 + dd];
#pragma unroll
            for (int i = 0; i < 4; i++)
#pragma unroll
                for (int j = 0; j < 4; j++)
                    s_acc[i][j] = fmaf(a[i], bb[j], s_acc[i][j]);
        }

        const bool diag = (kt == qb);

        // Online softmax per row; row stats reduced across 16 lanes (tx).
#pragma unroll
        for (int i = 0; i < 4; i++) {
            int qrow = qb * 64 + ty * 4 + i;
            float mx = -INFINITY;
#pragma unroll
            for (int j = 0; j < 4; j++) {
                float sv = s_acc[i][j] * 0.125f;
                if (diag) {
                    int kcol = kt * 64 + tx * 4 + j;
                    if (kcol > qrow) sv = -INFINITY;
                }
                s_acc[i][j] = sv;
                mx = fmaxf(mx, sv);
            }
#pragma unroll
            for (int off = 8; off > 0; off >>= 1)
                mx = fmaxf(mx, __shfl_xor_sync(0xffffffffu, mx, off));

            float mnew = fmaxf(m_i[i], mx);
            float scale = __expf(m_i[i] - mnew);   // m_i=-inf first time -> 0
            m_i[i] = mnew;

            float rowsum = 0.0f;
#pragma unroll
            for (int j = 0; j < 4; j++) {
                float p = __expf(s_acc[i][j] - mnew);  // -inf -> 0
                s_acc[i][j] = p;
                rowsum += p;
            }
#pragma unroll
            for (int off = 8; off > 0; off >>= 1)
                rowsum += __shfl_xor_sync(0xffffffffu, rowsum, off);

            l_i[i] = l_i[i] * scale + rowsum;
#pragma unroll
            for (int j = 0; j < 4; j++) o_acc[i][j] *= scale;
        }

        // Stage P to shared for the PV contraction.
#pragma unroll
        for (int i = 0; i < 4; i++)
#pragma unroll
            for (int j = 0; j < 4; j++)
                Ps[(ty * 4 + i) * 64 + tx * 4 + j] = s_acc[i][j];
        __syncthreads();

        // O += P @ V
        for (int kk = 0; kk < 64; kk++) {
            float pfr[4], vfr[4];
#pragma unroll
            for (int i = 0; i < 4; i++) pfr[i] = Ps[(ty * 4 + i) * 64 + kk];
#pragma unroll
            for (int j = 0; j < 4; j++) vfr[j] = Vs[kk * 64 + tx * 4 + j];
#pragma unroll
            for (int i = 0; i < 4; i++)
#pragma unroll
                for (int j = 0; j < 4; j++)
                    o_acc[i][j] = fmaf(pfr[i], vfr[j], o_acc[i][j]);
        }
        __syncthreads();
    }

    // Normalize and write O to [b, s, h*HD] layout.
#pragma unroll
    for (int i = 0; i < 4; i++) {
        float inv_l = 1.0f / l_i[i];
        int qrow = qb * 64 + ty * 4 + i;
        float* orow = O + ((size_t)b * SEQ + qrow) * (NH * HD) + h * HD;
#pragma unroll
        for (int j = 0; j < 4; j++)
            orow[tx * 4 + j] = o_acc[i][j] * inv_l;
    }
}

// ---------------------------------------------------------------------------
// kernel_launch
// inputs: 0=hidden_states 1=wq 2=wk 3=wv 4=wo 5=attention_mask 6=position_ids
// (mask/position_ids are the standard causal/arange forms; implemented directly)
// ---------------------------------------------------------------------------
extern "C" void kernel_launch(void* const* d_in, const int* in_sizes, int n_in,
                              void* d_out, int out_size)
{
    const float* hidden = (const float*)d_in[0];
    const float* wq = (const float*)d_in[1];
    const float* wk = (const float*)d_in[2];
    const float* wv = (const float*)d_in[3];
    const float* wo = (const float*)d_in[4];
    float* out = (float*)d_out;

    float *pq, *pk, *pv, *pattn;
    cudaGetSymbolAddress((void**)&pq, g_q);
    cudaGetSymbolAddress((void**)&pk, g_k);
    cudaGetSymbolAddress((void**)&pv, g_v);
    cudaGetSymbolAddress((void**)&pattn, g_attn);

    const int M = BSZ * SEQ;          // 4096
    dim3 blk(256);

    // QKV projections (scatter into [b,h,s,d])
    sgemm_kernel<<<dim3((NH * HD) / 128, M / 128), blk>>>(hidden, wq, pq, M, NH * HD, HIDDEN, NH);
    sgemm_kernel<<<dim3((NKV * HD) / 128, M / 128), blk>>>(hidden, wk, pk, M, NKV * HD, HIDDEN, NKV);
    sgemm_kernel<<<dim3((NKV * HD) / 128, M / 128), blk>>>(hidden, wv, pv, M, NKV * HD, HIDDEN, NKV);

    // RoPE on Q and K
    rope_kernel<<<(BSZ * NH * SEQ * 32 + 255) / 256, 256>>>(pq, BSZ * NH);
    rope_kernel<<<(BSZ * NKV * SEQ * 32 + 255) / 256, 256>>>(pk, BSZ * NKV);

    // Flash attention
    size_t fsm = (size_t)(64 * 64 + 64 * 65 + 64 * 64 + 64 * 64) * sizeof(float);
    cudaFuncSetAttribute(flash_kernel, cudaFuncAttributeMaxDynamicSharedMemorySize, (int)fsm);
    flash_kernel<<<dim3(SEQ / 64, NH, BSZ), blk, fsm>>>(pq, pk, pv, pattn);

    // Output projection
    sgemm_kernel<<<dim3(HIDDEN / 128, M / 128), blk>>>(pattn, wo, out, M, HIDDEN, HIDDEN, 0);
}

// round 2
// speedup vs baseline: 3.1757x; 3.1757x over previous
#include <cuda_runtime.h>
#include <math.h>
#include <stdint.h>

#define BSZ 2
#define SEQ 2048
#define HIDDEN 2048
#define NH 32
#define NKV 8
#define HD 64
#define NREP 4

// Scratch (static device arrays — no allocation).
__device__ float g_q[BSZ * NH * SEQ * HD];      // [b, h, s, d]
__device__ float g_k[BSZ * NKV * SEQ * HD];     // [b, kvh, s, d]
__device__ float g_v[BSZ * NKV * SEQ * HD];     // [b, kvh, s, d]
__device__ float g_attn[BSZ * SEQ * NH * HD];   // [b, s, h*d]

// ---------------------------------------------------------------------------
// TF32 helpers
// ---------------------------------------------------------------------------
__device__ __forceinline__ float tf32r(float x) {
    unsigned u;
    asm("cvt.rna.tf32.f32 %0, %1;" : "=r"(u) : "f"(x));
    return __uint_as_float(u);
}

__device__ __forceinline__ void mma8(float c[4],
                                     unsigned a0, unsigned a1, unsigned a2, unsigned a3,
                                     unsigned b0, unsigned b1) {
    asm volatile(
        "mma.sync.aligned.m16n8k8.row.col.f32.tf32.tf32.f32 "
        "{%0,%1,%2,%3}, {%4,%5,%6,%7}, {%8,%9}, {%0,%1,%2,%3};\n"
        : "+f"(c[0]), "+f"(c[1]), "+f"(c[2]), "+f"(c[3])
        : "r"(a0), "r"(a1), "r"(a2), "r"(a3), "r"(b0), "r"(b1));
}
#define F2U __float_as_uint

// ---------------------------------------------------------------------------
// TF32 tensor-core SGEMM: C = A[M,K] @ B[K,N], row-major.
// 128x128 block tile, BK=16, 256 threads (8 warps, 4x2), warp tile 32x64.
// scatter_heads == 0: C[m*N + n]
// scatter_heads  > 0: write to [b, h, s, d] (b=m/SEQ, s=m%SEQ, h=n/HD, d=n%HD)
// ---------------------------------------------------------------------------
#define ASTR 20     // As stride: 20 % 32 == 20, a-frag bank = (4r + k) -> conflict-free
#define BSTR 136    // Bs stride: 136 % 32 == 8, b-frag bank = (8k + n) -> conflict-free

__global__ __launch_bounds__(256, 2)
void gemm_tf32(const float* __restrict__ A, const float* __restrict__ B,
               float* __restrict__ C, int M, int N, int K, int scatter_heads)
{
    __shared__ float As[128 * ASTR];
    __shared__ float Bs[16 * BSTR];

    const int tid  = threadIdx.x;
    const int lane = tid & 31;
    const int warp = tid >> 5;
    const int wm   = warp >> 1;       // 0..3
    const int wn   = warp & 1;        // 0..1
    const int bx   = blockIdx.x;
    const int by   = blockIdx.y;
    const int q    = lane & 3;        // thread-in-group
    const int g    = lane >> 2;       // group id

    const float* Ag = A + (size_t)(by * 128) * K;
    const float* Bg = B + bx * 128;

    float acc[2][8][4];
#pragma unroll
    for (int mt = 0; mt < 2; mt++)
#pragma unroll
        for (int nt = 0; nt < 8; nt++)
#pragma unroll
            for (int j = 0; j < 4; j++) acc[mt][nt][j] = 0.0f;

    // Global load assignments (128x16 A tile, 16x128 B tile, float4)
    const int ar = tid >> 2;           // A row (second chunk: +64)
    const int ac = (tid & 3) << 2;     // A col (k)
    const int bk = tid >> 5;           // B k-row (second chunk: +8)
    const int bn = (tid & 31) << 2;    // B col (n)

    float4 av[2], bv[2];
    av[0] = *(const float4*)(Ag + (size_t)ar * K + ac);
    av[1] = *(const float4*)(Ag + (size_t)(ar + 64) * K + ac);
    bv[0] = *(const float4*)(Bg + (size_t)bk * N + bn);
    bv[1] = *(const float4*)(Bg + (size_t)(bk + 8) * N + bn);

    const int nkb = K >> 4;
    for (int kb = 0; kb < nkb; kb++) {
        // store staged tile to smem (convert to tf32 once here)
        {
            float4 w;
            w.x = tf32r(av[0].x); w.y = tf32r(av[0].y); w.z = tf32r(av[0].z); w.w = tf32r(av[0].w);
            *(float4*)&As[ar * ASTR + ac] = w;
            w.x = tf32r(av[1].x); w.y = tf32r(av[1].y); w.z = tf32r(av[1].z); w.w = tf32r(av[1].w);
            *(float4*)&As[(ar + 64) * ASTR + ac] = w;
            w.x = tf32r(bv[0].x); w.y = tf32r(bv[0].y); w.z = tf32r(bv[0].z); w.w = tf32r(bv[0].w);
            *(float4*)&Bs[bk * BSTR + bn] = w;
            w.x = tf32r(bv[1].x); w.y = tf32r(bv[1].y); w.z = tf32r(bv[1].z); w.w = tf32r(bv[1].w);
            *(float4*)&Bs[(bk + 8) * BSTR + bn] = w;
        }
        __syncthreads();

        // prefetch next tile while computing
        if (kb + 1 < nkb) {
            const float* Ag2 = Ag + (kb + 1) * 16;
            const float* Bg2 = Bg + (size_t)(kb + 1) * 16 * N;
            av[0] = *(const float4*)(Ag2 + (size_t)ar * K + ac);
            av[1] = *(const float4*)(Ag2 + (size_t)(ar + 64) * K + ac);
            bv[0] = *(const float4*)(Bg2 + (size_t)bk * N + bn);
            bv[1] = *(const float4*)(Bg2 + (size_t)(bk + 8) * N + bn);
        }

#pragma unroll
        for (int ks = 0; ks < 2; ks++) {
            const int k0 = ks * 8;
            unsigned a[2][4];
#pragma unroll
            for (int mt = 0; mt < 2; mt++) {
                const int r = wm * 32 + mt * 16 + g;
                a[mt][0] = F2U(As[r * ASTR + k0 + q]);
                a[mt][1] = F2U(As[(r + 8) * ASTR + k0 + q]);
                a[mt][2] = F2U(As[r * ASTR + k0 + 4 + q]);
                a[mt][3] = F2U(As[(r + 8) * ASTR + k0 + 4 + q]);
            }
#pragma unroll
            for (int nt = 0; nt < 8; nt++) {
                const int n = wn * 64 + nt * 8 + g;
                const unsigned b0 = F2U(Bs[(k0 + q) * BSTR + n]);
                const unsigned b1 = F2U(Bs[(k0 + 4 + q) * BSTR + n]);
                mma8(acc[0][nt], a[0][0], a[0][1], a[0][2], a[0][3], b0, b1);
                mma8(acc[1][nt], a[1][0], a[1][1], a[1][2], a[1][3], b0, b1);
            }
        }
        __syncthreads();
    }

    // Epilogue
#pragma unroll
    for (int mt = 0; mt < 2; mt++) {
        const int row = by * 128 + wm * 32 + mt * 16 + g;
#pragma unroll
        for (int nt = 0; nt < 8; nt++) {
            const int col = bx * 128 + wn * 64 + nt * 8 + (q << 1);
            if (scatter_heads > 0) {
                const int hh = col / HD, dd = col % HD;
#pragma unroll
                for (int rh = 0; rh < 2; rh++) {
                    const int m = row + rh * 8;
                    const int bb = m / SEQ, ss = m % SEQ;
                    float* p = C + (((size_t)bb * scatter_heads + hh) * SEQ + ss) * HD + dd;
                    p[0] = acc[mt][nt][rh * 2];
                    p[1] = acc[mt][nt][rh * 2 + 1];
                }
            } else {
                *(float2*)(C + (size_t)row * N + col) =
                    make_float2(acc[mt][nt][0], acc[mt][nt][1]);
                *(float2*)(C + (size_t)(row + 8) * N + col) =
                    make_float2(acc[mt][nt][2], acc[mt][nt][3]);
            }
        }
    }
}

// ---------------------------------------------------------------------------
// RoPE (in-place), fp32, replicating the reference math path.
// ---------------------------------------------------------------------------
__global__ void rope_kernel(float* __restrict__ x, int total_bh)
{
    int idx = blockIdx.x * blockDim.x + threadIdx.x;
    int total = total_bh * SEQ * 32;
    if (idx >= total) return;
    int p = idx & 31;
    int s = (idx >> 5) & (SEQ - 1);
    int bh = idx / (SEQ * 32);

    float* base = x + ((size_t)bh * SEQ + s) * HD;
    float inv = powf(10000.0f, -((float)(2 * p) / 64.0f));
    float ang = (float)s * inv;
    float c, si;
    sincosf(ang, &si, &c);
    float x1 = base[p];
    float x2 = base[p + 32];
    base[p]      = x1 * c - x2 * si;
    base[p + 32] = x2 * c + x1 * si;
}

// ---------------------------------------------------------------------------
// Flash attention, TF32 tensor cores, causal. 64-row Q tiles, 4 warps.
// Q/K/V: [b,(kv)h,s,d] fp32. Output: [b, s, h*HD].
// smem strides: Qs/Ks/Ps = 68 (A/B-frag bank-free), Vs = 72 (PV B-frag bank-free)
// ---------------------------------------------------------------------------
#define QSTR 68
#define VSTR 72

__global__ __launch_bounds__(128, 2)
void flash_tf32(const float* __restrict__ Q, const float* __restrict__ K,
                const float* __restrict__ V, float* __restrict__ O)
{
    extern __shared__ float sm[];
    float* Qs = sm;                       // [64][68]
    float* Ks = Qs + 64 * QSTR;           // [64][68]  rows = key index, cols = d
    float* Vs = Ks + 64 * QSTR;           // [64][72]  rows = key index, cols = d
    float* Ps = Vs + 64 * VSTR;           // [64][68]

    const int qb   = blockIdx.x;
    const int h    = blockIdx.y;
    const int b    = blockIdx.z;
    const int tid  = threadIdx.x;
    const int lane = tid & 31;
    const int warp = tid >> 5;
    const int q    = lane & 3;
    const int g    = lane >> 2;

    const float* Qg = Q + (((size_t)b * NH + h) * SEQ + qb * 64) * HD;
    const float* Kg = K + ((size_t)b * NKV + h / NREP) * SEQ * HD;
    const float* Vg = V + ((size_t)b * NKV + h / NREP) * SEQ * HD;

    // Load+convert Q tile: 64x64 floats -> 1024 float4 / 128 thr = 8 each
#pragma unroll
    for (int i = 0; i < 8; i++) {
        int f = tid + 128 * i;
        int r = f >> 4;
        int c4 = (f & 15) << 2;
        float4 v = *(const float4*)&Qg[r * HD + c4];
        float4 w;
        w.x = tf32r(v.x); w.y = tf32r(v.y); w.z = tf32r(v.z); w.w = tf32r(v.w);
        *(float4*)&Qs[r * QSTR + c4] = w;
    }

    float m_i[2], l_i[2], o_acc[8][4];
#pragma unroll
    for (int rh = 0; rh < 2; rh++) { m_i[rh] = -INFINITY; l_i[rh] = 0.0f; }
#pragma unroll
    for (int nt = 0; nt < 8; nt++)
#pragma unroll
        for (int j = 0; j < 4; j++) o_acc[nt][j] = 0.0f;

    const int rA = warp * 16 + g;               // this thread's base row in tile

    for (int kt = 0; kt <= qb; kt++) {
        // Load+convert K and V tiles
#pragma unroll
        for (int i = 0; i < 8; i++) {
            int f = tid + 128 * i;
            int r = f >> 4;
            int c4 = (f & 15) << 2;
            float4 kv = *(const float4*)&Kg[((size_t)kt * 64 + r) * HD + c4];
            float4 w;
            w.x = tf32r(kv.x); w.y = tf32r(kv.y); w.z = tf32r(kv.z); w.w = tf32r(kv.w);
            *(float4*)&Ks[r * QSTR + c4] = w;
            float4 vv = *(const float4*)&Vg[((size_t)kt * 64 + r) * HD + c4];
            w.x = tf32r(vv.x); w.y = tf32r(vv.y); w.z = tf32r(vv.z); w.w = tf32r(vv.w);
            *(float4*)&Vs[r * VSTR + c4] = w;
        }
        __syncthreads();

        // S = Q @ K^T : per-warp 16x64, 8 n-tiles, k = d = 64 (8 k-steps)
        float s_acc[8][4];
#pragma unroll
        for (int nt = 0; nt < 8; nt++)
#pragma unroll
            for (int j = 0; j < 4; j++) s_acc[nt][j] = 0.0f;

#pragma unroll
        for (int ks = 0; ks < 8; ks++) {
            const int k0 = ks * 8;
            const unsigned a0 = F2U(Qs[rA * QSTR + k0 + q]);
            const unsigned a1 = F2U(Qs[(rA + 8) * QSTR + k0 + q]);
            const unsigned a2 = F2U(Qs[rA * QSTR + k0 + 4 + q]);
            const unsigned a3 = F2U(Qs[(rA + 8) * QSTR + k0 + 4 + q]);
#pragma unroll
            for (int nt = 0; nt < 8; nt++) {
                const int n = nt * 8 + g;
                const unsigned b0 = F2U(Ks[n * QSTR + k0 + q]);
                const unsigned b1 = F2U(Ks[n * QSTR + k0 + 4 + q]);
                mma8(s_acc[nt], a0, a1, a2, a3, b0, b1);
            }
        }

        const bool diag = (kt == qb);

        // Online softmax per row-half
#pragma unroll
        for (int rh = 0; rh < 2; rh++) {
            const int rg = qb * 64 + rA + rh * 8;       // global query row
            float mx = -INFINITY;
#pragma unroll
            for (int nt = 0; nt < 8; nt++) {
#pragma unroll
                for (int j = 0; j < 2; j++) {
                    float sv = s_acc[nt][rh * 2 + j] * 0.125f;
                    if (diag) {
                        int cg = kt * 64 + nt * 8 + (q << 1) + j;
                        if (cg > rg) sv = -INFINITY;
                    }
                    s_acc[nt][rh * 2 + j] = sv;
                    mx = fmaxf(mx, sv);
                }
            }
            mx = fmaxf(mx, __shfl_xor_sync(0xffffffffu, mx, 1));
            mx = fmaxf(mx, __shfl_xor_sync(0xffffffffu, mx, 2));

            const float mnew = fmaxf(m_i[rh], mx);
            const float sc = __expf(m_i[rh] - mnew);
            m_i[rh] = mnew;

            float rs = 0.0f;
#pragma unroll
            for (int nt = 0; nt < 8; nt++) {
#pragma unroll
                for (int j = 0; j < 2; j++) {
                    float p = __expf(s_acc[nt][rh * 2 + j] - mnew);
                    s_acc[nt][rh * 2 + j] = p;
                    rs += p;
                }
            }
            rs += __shfl_xor_sync(0xffffffffu, rs, 1);
            rs += __shfl_xor_sync(0xffffffffu, rs, 2);

            l_i[rh] = l_i[rh] * sc + rs;
#pragma unroll
            for (int nt = 0; nt < 8; nt++) {
                o_acc[nt][rh * 2]     *= sc;
                o_acc[nt][rh * 2 + 1] *= sc;
            }
        }

        // Stage P to smem (per-warp private rows) for PV A-fragments
#pragma unroll
        for (int nt = 0; nt < 8; nt++) {
            const int c = nt * 8 + (q << 1);
            Ps[rA * QSTR + c]           = tf32r(s_acc[nt][0]);
            Ps[rA * QSTR + c + 1]       = tf32r(s_acc[nt][1]);
            Ps[(rA + 8) * QSTR + c]     = tf32r(s_acc[nt][2]);
            Ps[(rA + 8) * QSTR + c + 1] = tf32r(s_acc[nt][3]);
        }
        __syncwarp();

        // O += P @ V : k = 64 key cols (8 k-steps), n = d = 64 (8 n-tiles)
#pragma unroll
        for (int ks = 0; ks < 8; ks++) {
            const int k0 = ks * 8;
            const unsigned a0 = F2U(Ps[rA * QSTR + k0 + q]);
            const unsigned a1 = F2U(Ps[(rA + 8) * QSTR + k0 + q]);
            const unsigned a2 = F2U(Ps[rA * QSTR + k0 + 4 + q]);
            const unsigned a3 = F2U(Ps[(rA + 8) * QSTR + k0 + 4 + q]);
#pragma unroll
            for (int nt = 0; nt < 8; nt++) {
                const int n = nt * 8 + g;
                const unsigned b0 = F2U(Vs[(k0 + q) * VSTR + n]);
                const unsigned b1 = F2U(Vs[(k0 + 4 + q) * VSTR + n]);
                mma8(o_acc[nt], a0, a1, a2, a3, b0, b1);
            }
        }
        __syncthreads();
    }

    // Normalize and write O to [b, s, h*HD]
    const float inv0 = 1.0f / l_i[0];
    const float inv1 = 1.0f / l_i[1];
#pragma unroll
    for (int nt = 0; nt < 8; nt++) {
        const int c = nt * 8 + (q << 1);
        const int r0 = qb * 64 + rA;
        float* p0 = O + ((size_t)b * SEQ + r0) * (NH * HD) + h * HD + c;
        p0[0] = o_acc[nt][0] * inv0;
        p0[1] = o_acc[nt][1] * inv0;
        float* p1 = O + ((size_t)b * SEQ + r0 + 8) * (NH * HD) + h * HD + c;
        p1[0] = o_acc[nt][2] * inv1;
        p1[1] = o_acc[nt][3] * inv1;
    }
}

// ---------------------------------------------------------------------------
// kernel_launch
// ---------------------------------------------------------------------------
extern "C" void kernel_launch(void* const* d_in, const int* in_sizes, int n_in,
                              void* d_out, int out_size)
{
    const float* hidden = (const float*)d_in[0];
    const float* wq = (const float*)d_in[1];
    const float* wk = (const float*)d_in[2];
    const float* wv = (const float*)d_in[3];
    const float* wo = (const float*)d_in[4];
    float* out = (float*)d_out;

    float *pq, *pk, *pv, *pattn;
    cudaGetSymbolAddress((void**)&pq, g_q);
    cudaGetSymbolAddress((void**)&pk, g_k);
    cudaGetSymbolAddress((void**)&pv, g_v);
    cudaGetSymbolAddress((void**)&pattn, g_attn);

    const int M = BSZ * SEQ;          // 4096
    dim3 blk(256);

    // QKV projections (tf32 tensor cores, scatter into [b,h,s,d])
    gemm_tf32<<<dim3((NH * HD) / 128, M / 128), blk>>>(hidden, wq, pq, M, NH * HD, HIDDEN, NH);
    gemm_tf32<<<dim3((NKV * HD) / 128, M / 128), blk>>>(hidden, wk, pk, M, NKV * HD, HIDDEN, NKV);
    gemm_tf32<<<dim3((NKV * HD) / 128, M / 128), blk>>>(hidden, wv, pv, M, NKV * HD, HIDDEN, NKV);

    // RoPE on Q and K
    rope_kernel<<<(BSZ * NH * SEQ * 32 + 255) / 256, 256>>>(pq, BSZ * NH);
    rope_kernel<<<(BSZ * NKV * SEQ * 32 + 255) / 256, 256>>>(pk, BSZ * NKV);

    // Flash attention (tf32 tensor cores)
    size_t fsm = (size_t)(64 * QSTR * 3 + 64 * VSTR) * sizeof(float);
    cudaFuncSetAttribute(flash_tf32, cudaFuncAttributeMaxDynamicSharedMemorySize, (int)fsm);
    flash_tf32<<<dim3(SEQ / 64, NH, BSZ), dim3(128), fsm>>>(pq, pk, pv, pattn);

    // Output projection
    gemm_tf32<<<dim3(HIDDEN / 128, M / 128), blk>>>(pattn, wo, out, M, HIDDEN, HIDDEN, 0);
}

// round 3
// speedup vs baseline: 3.1802x; 1.0014x over previous
#include <cuda_runtime.h>
#include <math.h>
#include <stdint.h>

#define BSZ 2
#define SEQ 2048
#define HIDDEN 2048
#define NH 32
#define NKV 8
#define HD 64
#define NREP 4

// Scratch (static device arrays — no allocation).
__device__ float g_q[BSZ * NH * SEQ * HD];      // [b, h, s, d]
__device__ float g_k[BSZ * NKV * SEQ * HD];     // [b, kvh, s, d]
__device__ float g_v[BSZ * NKV * SEQ * HD];     // [b, kvh, s, d]
__device__ float g_attn[BSZ * SEQ * NH * HD];   // [b, s, h*d]

// ---------------------------------------------------------------------------
// TF32 helpers
// ---------------------------------------------------------------------------
__device__ __forceinline__ float tf32r(float x) {
    unsigned u;
    asm("cvt.rna.tf32.f32 %0, %1;" : "=r"(u) : "f"(x));
    return __uint_as_float(u);
}

__device__ __forceinline__ void mma8(float c[4],
                                     unsigned a0, unsigned a1, unsigned a2, unsigned a3,
                                     unsigned b0, unsigned b1) {
    asm volatile(
        "mma.sync.aligned.m16n8k8.row.col.f32.tf32.tf32.f32 "
        "{%0,%1,%2,%3}, {%4,%5,%6,%7}, {%8,%9}, {%0,%1,%2,%3};\n"
        : "+f"(c[0]), "+f"(c[1]), "+f"(c[2]), "+f"(c[3])
        : "r"(a0), "r"(a1), "r"(a2), "r"(a3), "r"(b0), "r"(b1));
}
#define F2U __float_as_uint

// ---------------------------------------------------------------------------
// TF32 tensor-core SGEMM: C = A[M,K] @ B[K,N], row-major.
// 128x128 block tile, BK=16, 256 threads (8 warps, 4x2), warp tile 32x64.
// scatter_heads == 0: C[m*N + n]
// scatter_heads  > 0: write to [b, h, s, d] (b=m/SEQ, s=m%SEQ, h=n/HD, d=n%HD)
// ---------------------------------------------------------------------------
#define ASTR 20     // As stride: 20 % 32 == 20, a-frag bank = (4r + k) -> conflict-free
#define BSTR 136    // Bs stride: 136 % 32 == 8, b-frag bank = (8k + n) -> conflict-free

__global__ __launch_bounds__(256, 2)
void gemm_tf32(const float* __restrict__ A, const float* __restrict__ B,
               float* __restrict__ C, int M, int N, int K, int scatter_heads)
{
    __shared__ float As[128 * ASTR];
    __shared__ float Bs[16 * BSTR];

    const int tid  = threadIdx.x;
    const int lane = tid & 31;
    const int warp = tid >> 5;
    const int wm   = warp >> 1;       // 0..3
    const int wn   = warp & 1;        // 0..1
    const int bx   = blockIdx.x;
    const int by   = blockIdx.y;
    const int q    = lane & 3;        // thread-in-group
    const int g    = lane >> 2;       // group id

    const float* Ag = A + (size_t)(by * 128) * K;
    const float* Bg = B + bx * 128;

    float acc[2][8][4];
#pragma unroll
    for (int mt = 0; mt < 2; mt++)
#pragma unroll
        for (int nt = 0; nt < 8; nt++)
#pragma unroll
            for (int j = 0; j < 4; j++) acc[mt][nt][j] = 0.0f;

    // Global load assignments (128x16 A tile, 16x128 B tile, float4)
    const int ar = tid >> 2;           // A row (second chunk: +64)
    const int ac = (tid & 3) << 2;     // A col (k)
    const int bk = tid >> 5;           // B k-row (second chunk: +8)
    const int bn = (tid & 31) << 2;    // B col (n)

    float4 av[2], bv[2];
    av[0] = *(const float4*)(Ag + (size_t)ar * K + ac);
    av[1] = *(const float4*)(Ag + (size_t)(ar + 64) * K + ac);
    bv[0] = *(const float4*)(Bg + (size_t)bk * N + bn);
    bv[1] = *(const float4*)(Bg + (size_t)(bk + 8) * N + bn);

    const int nkb = K >> 4;
    for (int kb = 0; kb < nkb; kb++) {
        // store staged tile to smem (convert to tf32 once here)
        {
            float4 w;
            w.x = tf32r(av[0].x); w.y = tf32r(av[0].y); w.z = tf32r(av[0].z); w.w = tf32r(av[0].w);
            *(float4*)&As[ar * ASTR + ac] = w;
            w.x = tf32r(av[1].x); w.y = tf32r(av[1].y); w.z = tf32r(av[1].z); w.w = tf32r(av[1].w);
            *(float4*)&As[(ar + 64) * ASTR + ac] = w;
            w.x = tf32r(bv[0].x); w.y = tf32r(bv[0].y); w.z = tf32r(bv[0].z); w.w = tf32r(bv[0].w);
            *(float4*)&Bs[bk * BSTR + bn] = w;
            w.x = tf32r(bv[1].x); w.y = tf32r(bv[1].y); w.z = tf32r(bv[1].z); w.w = tf32r(bv[1].w);
            *(float4*)&Bs[(bk + 8) * BSTR + bn] = w;
        }
        __syncthreads();

        // prefetch next tile while computing
        if (kb + 1 < nkb) {
            const float* Ag2 = Ag + (kb + 1) * 16;
            const float* Bg2 = Bg + (size_t)(kb + 1) * 16 * N;
            av[0] = *(const float4*)(Ag2 + (size_t)ar * K + ac);
            av[1] = *(const float4*)(Ag2 + (size_t)(ar + 64) * K + ac);
            bv[0] = *(const float4*)(Bg2 + (size_t)bk * N + bn);
            bv[1] = *(const float4*)(Bg2 + (size_t)(bk + 8) * N + bn);
        }

#pragma unroll
        for (int ks = 0; ks < 2; ks++) {
            const int k0 = ks * 8;
            unsigned a[2][4];
#pragma unroll
            for (int mt = 0; mt < 2; mt++) {
                const int r = wm * 32 + mt * 16 + g;
                a[mt][0] = F2U(As[r * ASTR + k0 + q]);
                a[mt][1] = F2U(As[(r + 8) * ASTR + k0 + q]);
                a[mt][2] = F2U(As[r * ASTR + k0 + 4 + q]);
                a[mt][3] = F2U(As[(r + 8) * ASTR + k0 + 4 + q]);
            }
#pragma unroll
            for (int nt = 0; nt < 8; nt++) {
                const int n = wn * 64 + nt * 8 + g;
                const unsigned b0 = F2U(Bs[(k0 + q) * BSTR + n]);
                const unsigned b1 = F2U(Bs[(k0 + 4 + q) * BSTR + n]);
                mma8(acc[0][nt], a[0][0], a[0][1], a[0][2], a[0][3], b0, b1);
                mma8(acc[1][nt], a[1][0], a[1][1], a[1][2], a[1][3], b0, b1);
            }
        }
        __syncthreads();
    }

    // Epilogue
#pragma unroll
    for (int mt = 0; mt < 2; mt++) {
        const int row = by * 128 + wm * 32 + mt * 16 + g;
#pragma unroll
        for (int nt = 0; nt < 8; nt++) {
            const int col = bx * 128 + wn * 64 + nt * 8 + (q << 1);
            if (scatter_heads > 0) {
                const int hh = col / HD, dd = col % HD;
#pragma unroll
                for (int rh = 0; rh < 2; rh++) {
                    const int m = row + rh * 8;
                    const int bb = m / SEQ, ss = m % SEQ;
                    float* p = C + (((size_t)bb * scatter_heads + hh) * SEQ + ss) * HD + dd;
                    p[0] = acc[mt][nt][rh * 2];
                    p[1] = acc[mt][nt][rh * 2 + 1];
                }
            } else {
                *(float2*)(C + (size_t)row * N + col) =
                    make_float2(acc[mt][nt][0], acc[mt][nt][1]);
                *(float2*)(C + (size_t)(row + 8) * N + col) =
                    make_float2(acc[mt][nt][2], acc[mt][nt][3]);
            }
        }
    }
}

// ---------------------------------------------------------------------------
// RoPE (in-place), fp32, replicating the reference math path.
// ---------------------------------------------------------------------------
__global__ void rope_kernel(float* __restrict__ x, int total_bh)
{
    int idx = blockIdx.x * blockDim.x + threadIdx.x;
    int total = total_bh * SEQ * 32;
    if (idx >= total) return;
    int p = idx & 31;
    int s = (idx >> 5) & (SEQ - 1);
    int bh = idx / (SEQ * 32);

    float* base = x + ((size_t)bh * SEQ + s) * HD;
    float inv = powf(10000.0f, -((float)(2 * p) / 64.0f));
    float ang = (float)s * inv;
    float c, si;
    sincosf(ang, &si, &c);
    float x1 = base[p];
    float x2 = base[p + 32];
    base[p]      = x1 * c - x2 * si;
    base[p + 32] = x2 * c + x1 * si;
}

// ---------------------------------------------------------------------------
// Flash attention, TF32 tensor cores, causal. 64-row Q tiles, 4 warps.
// Q/K/V: [b,(kv)h,s,d] fp32. Output: [b, s, h*HD].
// smem strides: Qs/Ks/Ps = 68 (A/B-frag bank-free), Vs = 72 (PV B-frag bank-free)
// ---------------------------------------------------------------------------
#define QSTR 68
#define VSTR 72

__global__ __launch_bounds__(128, 2)
void flash_tf32(const float* __restrict__ Q, const float* __restrict__ K,
                const float* __restrict__ V, float* __restrict__ O)
{
    extern __shared__ float sm[];
    float* Qs = sm;                       // [64][68]
    float* Ks = Qs + 64 * QSTR;           // [64][68]  rows = key index, cols = d
    float* Vs = Ks + 64 * QSTR;           // [64][72]  rows = key index, cols = d
    float* Ps = Vs + 64 * VSTR;           // [64][68]

    const int qb   = blockIdx.x;
    const int h    = blockIdx.y;
    const int b    = blockIdx.z;
    const int tid  = threadIdx.x;
    const int lane = tid & 31;
    const int warp = tid >> 5;
    const int q    = lane & 3;
    const int g    = lane >> 2;

    const float* Qg = Q + (((size_t)b * NH + h) * SEQ + qb * 64) * HD;
    const float* Kg = K + ((size_t)b * NKV + h / NREP) * SEQ * HD;
    const float* Vg = V + ((size_t)b * NKV + h / NREP) * SEQ * HD;

    // Load+convert Q tile: 64x64 floats -> 1024 float4 / 128 thr = 8 each
#pragma unroll
    for (int i = 0; i < 8; i++) {
        int f = tid + 128 * i;
        int r = f >> 4;
        int c4 = (f & 15) << 2;
        float4 v = *(const float4*)&Qg[r * HD + c4];
        float4 w;
        w.x = tf32r(v.x); w.y = tf32r(v.y); w.z = tf32r(v.z); w.w = tf32r(v.w);
        *(float4*)&Qs[r * QSTR + c4] = w;
    }

    float m_i[2], l_i[2], o_acc[8][4];
#pragma unroll
    for (int rh = 0; rh < 2; rh++) { m_i[rh] = -INFINITY; l_i[rh] = 0.0f; }
#pragma unroll
    for (int nt = 0; nt < 8; nt++)
#pragma unroll
        for (int j = 0; j < 4; j++) o_acc[nt][j] = 0.0f;

    const int rA = warp * 16 + g;               // this thread's base row in tile

    for (int kt = 0; kt <= qb; kt++) {
        // Load+convert K and V tiles
#pragma unroll
        for (int i = 0; i < 8; i++) {
            int f = tid + 128 * i;
            int r = f >> 4;
            int c4 = (f & 15) << 2;
            float4 kv = *(const float4*)&Kg[((size_t)kt * 64 + r) * HD + c4];
            float4 w;
            w.x = tf32r(kv.x); w.y = tf32r(kv.y); w.z = tf32r(kv.z); w.w = tf32r(kv.w);
            *(float4*)&Ks[r * QSTR + c4] = w;
            float4 vv = *(const float4*)&Vg[((size_t)kt * 64 + r) * HD + c4];
            w.x = tf32r(vv.x); w.y = tf32r(vv.y); w.z = tf32r(vv.z); w.w = tf32r(vv.w);
            *(float4*)&Vs[r * VSTR + c4] = w;
        }
        __syncthreads();

        // S = Q @ K^T : per-warp 16x64, 8 n-tiles, k = d = 64 (8 k-steps)
        float s_acc[8][4];
#pragma unroll
        for (int nt = 0; nt < 8; nt++)
#pragma unroll
            for (int j = 0; j < 4; j++) s_acc[nt][j] = 0.0f;

#pragma unroll
        for (int ks = 0; ks < 8; ks++) {
            const int k0 = ks * 8;
            const unsigned a0 = F2U(Qs[rA * QSTR + k0 + q]);
            const unsigned a1 = F2U(Qs[(rA + 8) * QSTR + k0 + q]);
            const unsigned a2 = F2U(Qs[rA * QSTR + k0 + 4 + q]);
            const unsigned a3 = F2U(Qs[(rA + 8) * QSTR + k0 + 4 + q]);
#pragma unroll
            for (int nt = 0; nt < 8; nt++) {
                const int n = nt * 8 + g;
                const unsigned b0 = F2U(Ks[n * QSTR + k0 + q]);
                const unsigned b1 = F2U(Ks[n * QSTR + k0 + 4 + q]);
                mma8(s_acc[nt], a0, a1, a2, a3, b0, b1);
            }
        }

        const bool diag = (kt == qb);

        // Online softmax per row-half
#pragma unroll
        for (int rh = 0; rh < 2; rh++) {
            const int rg = qb * 64 + rA + rh * 8;       // global query row
            float mx = -INFINITY;
#pragma unroll
            for (int nt = 0; nt < 8; nt++) {
#pragma unroll
                for (int j = 0; j < 2; j++) {
                    float sv = s_acc[nt][rh * 2 + j] * 0.125f;
                    if (diag) {
                        int cg = kt * 64 + nt * 8 + (q << 1) + j;
                        if (cg > rg) sv = -INFINITY;
                    }
                    s_acc[nt][rh * 2 + j] = sv;
                    mx = fmaxf(mx, sv);
                }
            }
            mx = fmaxf(mx, __shfl_xor_sync(0xffffffffu, mx, 1));
            mx = fmaxf(mx, __shfl_xor_sync(0xffffffffu, mx, 2));

            const float mnew = fmaxf(m_i[rh], mx);
            const float sc = __expf(m_i[rh] - mnew);
            m_i[rh] = mnew;

            float rs = 0.0f;
#pragma unroll
            for (int nt = 0; nt < 8; nt++) {
#pragma unroll
                for (int j = 0; j < 2; j++) {
                    float p = __expf(s_acc[nt][rh * 2 + j] - mnew);
                    s_acc[nt][rh * 2 + j] = p;
                    rs += p;
                }
            }
            rs += __shfl_xor_sync(0xffffffffu, rs, 1);
            rs += __shfl_xor_sync(0xffffffffu, rs, 2);

            l_i[rh] = l_i[rh] * sc + rs;
#pragma unroll
            for (int nt = 0; nt < 8; nt++) {
                o_acc[nt][rh * 2]     *= sc;
                o_acc[nt][rh * 2 + 1] *= sc;
            }
        }

        // Stage P to smem (per-warp private rows) for PV A-fragments
#pragma unroll
        for (int nt = 0; nt < 8; nt++) {
            const int c = nt * 8 + (q << 1);
            Ps[rA * QSTR + c]           = tf32r(s_acc[nt][0]);
            Ps[rA * QSTR + c + 1]       = tf32r(s_acc[nt][1]);
            Ps[(rA + 8) * QSTR + c]     = tf32r(s_acc[nt][2]);
            Ps[(rA + 8) * QSTR + c + 1] = tf32r(s_acc[nt][3]);
        }
        __syncwarp();

        // O += P @ V : k = 64 key cols (8 k-steps), n = d = 64 (8 n-tiles)
#pragma unroll
        for (int ks = 0; ks < 8; ks++) {
            const int k0 = ks * 8;
            const unsigned a0 = F2U(Ps[rA * QSTR + k0 + q]);
            const unsigned a1 = F2U(Ps[(rA + 8) * QSTR + k0 + q]);
            const unsigned a2 = F2U(Ps[rA * QSTR + k0 + 4 + q]);
            const unsigned a3 = F2U(Ps[(rA + 8) * QSTR + k0 + 4 + q]);
#pragma unroll
            for (int nt = 0; nt < 8; nt++) {
                const int n = nt * 8 + g;
                const unsigned b0 = F2U(Vs[(k0 + q) * VSTR + n]);
                const unsigned b1 = F2U(Vs[(k0 + 4 + q) * VSTR + n]);
                mma8(o_acc[nt], a0, a1, a2, a3, b0, b1);
            }
        }
        __syncthreads();
    }

    // Normalize and write O to [b, s, h*HD]
    const float inv0 = 1.0f / l_i[0];
    const float inv1 = 1.0f / l_i[1];
#pragma unroll
    for (int nt = 0; nt < 8; nt++) {
        const int c = nt * 8 + (q << 1);
        const int r0 = qb * 64 + rA;
        float* p0 = O + ((size_t)b * SEQ + r0) * (NH * HD) + h * HD + c;
        p0[0] = o_acc[nt][0] * inv0;
        p0[1] = o_acc[nt][1] * inv0;
        float* p1 = O + ((size_t)b * SEQ + r0 + 8) * (NH * HD) + h * HD + c;
        p1[0] = o_acc[nt][2] * inv1;
        p1[1] = o_acc[nt][3] * inv1;
    }
}

// ---------------------------------------------------------------------------
// kernel_launch
// ---------------------------------------------------------------------------
extern "C" void kernel_launch(void* const* d_in, const int* in_sizes, int n_in,
                              void* d_out, int out_size)
{
    const float* hidden = (const float*)d_in[0];
    const float* wq = (const float*)d_in[1];
    const float* wk = (const float*)d_in[2];
    const float* wv = (const float*)d_in[3];
    const float* wo = (const float*)d_in[4];
    float* out = (float*)d_out;

    float *pq, *pk, *pv, *pattn;
    cudaGetSymbolAddress((void**)&pq, g_q);
    cudaGetSymbolAddress((void**)&pk, g_k);
    cudaGetSymbolAddress((void**)&pv, g_v);
    cudaGetSymbolAddress((void**)&pattn, g_attn);

    const int M = BSZ * SEQ;          // 4096
    dim3 blk(256);

    // QKV projections (tf32 tensor cores, scatter into [b,h,s,d])
    gemm_tf32<<<dim3((NH * HD) / 128, M / 128), blk>>>(hidden, wq, pq, M, NH * HD, HIDDEN, NH);
    gemm_tf32<<<dim3((NKV * HD) / 128, M / 128), blk>>>(hidden, wk, pk, M, NKV * HD, HIDDEN, NKV);
    gemm_tf32<<<dim3((NKV * HD) / 128, M / 128), blk>>>(hidden, wv, pv, M, NKV * HD, HIDDEN, NKV);

    // RoPE on Q and K
    rope_kernel<<<(BSZ * NH * SEQ * 32 + 255) / 256, 256>>>(pq, BSZ * NH);
    rope_kernel<<<(BSZ * NKV * SEQ * 32 + 255) / 256, 256>>>(pk, BSZ * NKV);

    // Flash attention (tf32 tensor cores)
    size_t fsm = (size_t)(64 * QSTR * 3 + 64 * VSTR) * sizeof(float);
    cudaFuncSetAttribute(flash_tf32, cudaFuncAttributeMaxDynamicSharedMemorySize, (int)fsm);
    flash_tf32<<<dim3(SEQ / 64, NH, BSZ), dim3(128), fsm>>>(pq, pk, pv, pattn);

    // Output projection
    gemm_tf32<<<dim3(HIDDEN / 128, M / 128), blk>>>(pattn, wo, out, M, HIDDEN, HIDDEN, 0);
}

// round 4
// speedup vs baseline: 3.4654x; 1.0897x over previous
#include <cuda_runtime.h>
#include <math.h>
#include <stdint.h>

#define BSZ 2
#define SEQ 2048
#define HIDDEN 2048
#define NH 32
#define NKV 8
#define HD 64
#define NREP 4

// Scratch (static device arrays — no allocation).
__device__ float g_q[BSZ * NH * SEQ * HD];      // [b, h, s, d]
__device__ float g_k[BSZ * NKV * SEQ * HD];     // [b, kvh, s, d]
__device__ float g_v[BSZ * NKV * SEQ * HD];     // [b, kvh, s, d]
__device__ float g_attn[BSZ * SEQ * NH * HD];   // [b, s, h*d] (tf32-rounded)

// tf32-rounded copies of the GEMM inputs (rounded once per launch).
__device__ float g_ht[BSZ * SEQ * HIDDEN];
__device__ float g_wqt[HIDDEN * NH * HD];
__device__ float g_wkt[HIDDEN * NKV * HD];
__device__ float g_wvt[HIDDEN * NKV * HD];
__device__ float g_wot[NH * HD * HIDDEN];

// ---------------------------------------------------------------------------
// TF32 helpers
// ---------------------------------------------------------------------------
__device__ __forceinline__ float tf32r(float x) {
    unsigned u;
    asm("cvt.rna.tf32.f32 %0, %1;" : "=r"(u) : "f"(x));
    return __uint_as_float(u);
}

__device__ __forceinline__ void mma8(float c[4],
                                     unsigned a0, unsigned a1, unsigned a2, unsigned a3,
                                     unsigned b0, unsigned b1) {
    asm volatile(
        "mma.sync.aligned.m16n8k8.row.col.f32.tf32.tf32.f32 "
        "{%0,%1,%2,%3}, {%4,%5,%6,%7}, {%8,%9}, {%0,%1,%2,%3};\n"
        : "+f"(c[0]), "+f"(c[1]), "+f"(c[2]), "+f"(c[3])
        : "r"(a0), "r"(a1), "r"(a2), "r"(a3), "r"(b0), "r"(b1));
}
#define F2U __float_as_uint

// ---------------------------------------------------------------------------
// Prologue: round hidden + weights to tf32 (float4 grid-stride over segments)
// ---------------------------------------------------------------------------
#define N_H4  (BSZ * SEQ * HIDDEN / 4)            // 2097152
#define N_WQ4 (HIDDEN * NH * HD / 4)              // 1048576
#define N_WK4 (HIDDEN * NKV * HD / 4)             // 262144
#define N_WV4 N_WK4
#define N_WO4 N_WQ4
#define CUM1 N_H4
#define CUM2 (CUM1 + N_WQ4)
#define CUM3 (CUM2 + N_WK4)
#define CUM4 (CUM3 + N_WV4)
#define CUM5 (CUM4 + N_WO4)

__global__ void conv_tf32(const float* __restrict__ h, const float* __restrict__ wq,
                          const float* __restrict__ wk, const float* __restrict__ wv,
                          const float* __restrict__ wo,
                          float* __restrict__ ht, float* __restrict__ wqt,
                          float* __restrict__ wkt, float* __restrict__ wvt,
                          float* __restrict__ wot)
{
    int i = blockIdx.x * blockDim.x + threadIdx.x;
    if (i >= CUM5) return;
    const float4* s;
    float4* d;
    if (i < CUM1)      { s = (const float4*)h  + i;          d = (float4*)ht  + i; }
    else if (i < CUM2) { s = (const float4*)wq + (i - CUM1); d = (float4*)wqt + (i - CUM1); }
    else if (i < CUM3) { s = (const float4*)wk + (i - CUM2); d = (float4*)wkt + (i - CUM2); }
    else if (i < CUM4) { s = (const float4*)wv + (i - CUM3); d = (float4*)wvt + (i - CUM3); }
    else               { s = (const float4*)wo + (i - CUM4); d = (float4*)wot + (i - CUM4); }
    float4 v = *s;
    v.x = tf32r(v.x); v.y = tf32r(v.y); v.z = tf32r(v.z); v.w = tf32r(v.w);
    *d = v;
}

// ---------------------------------------------------------------------------
// Shared GEMM mainloop: 128x128 tile, BK=16, 256 thr (8 warps 4x2, warp 32x64)
// cp.async 2-stage double buffer. Inputs are already tf32-rounded.
// ---------------------------------------------------------------------------
#define ASTR 20     // As stride: a-frag bank (4r + k) -> conflict-free
#define BSTR 136    // Bs stride: b-frag bank (8k + n) -> conflict-free

__device__ __forceinline__ void gemm_mainloop(
    const float* __restrict__ Ag, const float* __restrict__ Bg,
    int K, int N, float acc[2][8][4], float* As, float* Bs)
{
    const int tid  = threadIdx.x;
    const int lane = tid & 31;
    const int warp = tid >> 5;
    const int wm   = warp >> 1;
    const int wn   = warp & 1;
    const int q    = lane & 3;
    const int g    = lane >> 2;

    const int ar = tid >> 2;
    const int ac = (tid & 3) << 2;
    const int bk = tid >> 5;
    const int bn = (tid & 31) << 2;

    uint32_t sA = (uint32_t)__cvta_generic_to_shared(As);
    uint32_t sB = (uint32_t)__cvta_generic_to_shared(Bs);

#define ISSUE(kb, st) do {                                                          \
    const float* a0 = Ag + (size_t)ar * K + (kb) * 16 + ac;                         \
    uint32_t da = sA + (uint32_t)(((st) * 128 * ASTR + ar * ASTR + ac) * 4);        \
    asm volatile("cp.async.ca.shared.global [%0], [%1], 16;" :: "r"(da), "l"(a0));  \
    asm volatile("cp.async.ca.shared.global [%0], [%1], 16;"                        \
                 :: "r"(da + 64u * ASTR * 4u), "l"(a0 + (size_t)64 * K));           \
    const float* b0 = Bg + (size_t)((kb) * 16 + bk) * N + bn;                       \
    uint32_t db = sB + (uint32_t)(((st) * 16 * BSTR + bk * BSTR + bn) * 4);         \
    asm volatile("cp.async.ca.shared.global [%0], [%1], 16;" :: "r"(db), "l"(b0));  \
    asm volatile("cp.async.ca.shared.global [%0], [%1], 16;"                        \
                 :: "r"(db + 8u * BSTR * 4u), "l"(b0 + (size_t)8 * N));             \
    asm volatile("cp.async.commit_group;");                                         \
} while (0)

    const int nkb = K >> 4;
    ISSUE(0, 0);
    for (int kb = 0; kb < nkb; kb++) {
        const int st = kb & 1;
        if (kb + 1 < nkb) {
            ISSUE(kb + 1, st ^ 1);
            asm volatile("cp.async.wait_group 1;");
        } else {
            asm volatile("cp.async.wait_group 0;");
        }
        __syncthreads();

        const float* A0 = As + st * 128 * ASTR;
        const float* B0 = Bs + st * 16 * BSTR;
#pragma unroll
        for (int ks = 0; ks < 2; ks++) {
            const int k0 = ks * 8;
            unsigned a[2][4];
#pragma unroll
            for (int mt = 0; mt < 2; mt++) {
                const int r = wm * 32 + mt * 16 + g;
                a[mt][0] = F2U(A0[r * ASTR + k0 + q]);
                a[mt][1] = F2U(A0[(r + 8) * ASTR + k0 + q]);
                a[mt][2] = F2U(A0[r * ASTR + k0 + 4 + q]);
                a[mt][3] = F2U(A0[(r + 8) * ASTR + k0 + 4 + q]);
            }
#pragma unroll
            for (int nt = 0; nt < 8; nt++) {
                const int n = wn * 64 + nt * 8 + g;
                const unsigned b0 = F2U(B0[(k0 + q) * BSTR + n]);
                const unsigned b1 = F2U(B0[(k0 + 4 + q) * BSTR + n]);
                mma8(acc[0][nt], a[0][0], a[0][1], a[0][2], a[0][3], b0, b1);
                mma8(acc[1][nt], a[1][0], a[1][1], a[1][2], a[1][3], b0, b1);
            }
        }
        __syncthreads();
    }
#undef ISSUE
}

// ---------------------------------------------------------------------------
// Fused QKV projection + RoPE epilogue, scattering into [b, h, s, d].
// grid.x = 24: bx<16 -> Q, bx<20 -> K, else V. grid.y = 32 (M tiles).
// ---------------------------------------------------------------------------
__global__ __launch_bounds__(256, 2)
void qkv_gemm(const float* __restrict__ hidden)
{
    __shared__ float As[2 * 128 * ASTR];
    __shared__ float Bs[2 * 16 * BSTR];

    const int bx = blockIdx.x, by = blockIdx.y;
    const int tid = threadIdx.x;
    const int lane = tid & 31, warp = tid >> 5;
    const int wm = warp >> 1, wn = warp & 1;
    const int q = lane & 3, g = lane >> 2;

    const float* W;
    float* Out;
    int N, cb, heads;
    bool rope;
    if (bx < 16)      { W = g_wqt; Out = g_q; N = NH * HD;  cb = bx * 128;        heads = NH;  rope = true;  }
    else if (bx < 20) { W = g_wkt; Out = g_k; N = NKV * HD; cb = (bx - 16) * 128; heads = NKV; rope = true;  }
    else              { W = g_wvt; Out = g_v; N = NKV * HD; cb = (bx - 20) * 128; heads = NKV; rope = false; }

    float acc[2][8][4];
#pragma unroll
    for (int mt = 0; mt < 2; mt++)
#pragma unroll
        for (int nt = 0; nt < 8; nt++)
#pragma unroll
            for (int j = 0; j < 4; j++) acc[mt][nt][j] = 0.0f;

    gemm_mainloop(hidden + (size_t)(by * 128) * HIDDEN, W + cb, HIDDEN, N, acc, As, Bs);

    // RoPE in registers: pair (nt, nt+4) holds head-dims (d, d+32), d = nt*8+q*2+j
    if (rope) {
        float invf[8];
#pragma unroll
        for (int ntp = 0; ntp < 4; ntp++)
#pragma unroll
            for (int j = 0; j < 2; j++)
                invf[ntp * 2 + j] =
                    powf(10000.0f, -((float)(2 * (ntp * 8 + (q << 1) + j)) / 64.0f));
#pragma unroll
        for (int mt = 0; mt < 2; mt++) {
#pragma unroll
            for (int rh = 0; rh < 2; rh++) {
                const int m = by * 128 + wm * 32 + mt * 16 + g + rh * 8;
                const float s = (float)(m & (SEQ - 1));
#pragma unroll
                for (int ntp = 0; ntp < 4; ntp++) {
#pragma unroll
                    for (int j = 0; j < 2; j++) {
                        float c, si;
                        sincosf(s * invf[ntp * 2 + j], &si, &c);
                        const float x1 = acc[mt][ntp][rh * 2 + j];
                        const float x2 = acc[mt][ntp + 4][rh * 2 + j];
                        acc[mt][ntp][rh * 2 + j]     = x1 * c - x2 * si;
                        acc[mt][ntp + 4][rh * 2 + j] = x2 * c + x1 * si;
                    }
                }
            }
        }
    }

    // Scatter store to [b, h, s, d]
#pragma unroll
    for (int mt = 0; mt < 2; mt++) {
        const int row = by * 128 + wm * 32 + mt * 16 + g;
#pragma unroll
        for (int nt = 0; nt < 8; nt++) {
            const int col = cb + wn * 64 + nt * 8 + (q << 1);
            const int hh = col / HD, dd = col & (HD - 1);
#pragma unroll
            for (int rh = 0; rh < 2; rh++) {
                const int m = row + rh * 8;
                const int bb = m >> 11, ss = m & (SEQ - 1);
                float* p = Out + (((size_t)bb * heads + hh) * SEQ + ss) * HD + dd;
                p[0] = acc[mt][nt][rh * 2];
                p[1] = acc[mt][nt][rh * 2 + 1];
            }
        }
    }
}

// ---------------------------------------------------------------------------
// Output projection: C[M,2048] = g_attn[M,2048] @ wo_t, linear store.
// ---------------------------------------------------------------------------
__global__ __launch_bounds__(256, 2)
void gemm_o(const float* __restrict__ A, const float* __restrict__ B,
            float* __restrict__ C)
{
    __shared__ float As[2 * 128 * ASTR];
    __shared__ float Bs[2 * 16 * BSTR];

    const int bx = blockIdx.x, by = blockIdx.y;
    const int tid = threadIdx.x;
    const int lane = tid & 31, warp = tid >> 5;
    const int wm = warp >> 1, wn = warp & 1;
    const int q = lane & 3, g = lane >> 2;
    const int N = HIDDEN;

    float acc[2][8][4];
#pragma unroll
    for (int mt = 0; mt < 2; mt++)
#pragma unroll
        for (int nt = 0; nt < 8; nt++)
#pragma unroll
            for (int j = 0; j < 4; j++) acc[mt][nt][j] = 0.0f;

    gemm_mainloop(A + (size_t)(by * 128) * HIDDEN, B + bx * 128, HIDDEN, N, acc, As, Bs);

#pragma unroll
    for (int mt = 0; mt < 2; mt++) {
        const int row = by * 128 + wm * 32 + mt * 16 + g;
#pragma unroll
        for (int nt = 0; nt < 8; nt++) {
            const int col = bx * 128 + wn * 64 + nt * 8 + (q << 1);
            *(float2*)(C + (size_t)row * N + col) =
                make_float2(acc[mt][nt][0], acc[mt][nt][1]);
            *(float2*)(C + (size_t)(row + 8) * N + col) =
                make_float2(acc[mt][nt][2], acc[mt][nt][3]);
        }
    }
}

// ---------------------------------------------------------------------------
// Flash attention, TF32 tensor cores, causal. 64-row Q tiles, 4 warps, occ 3.
// Q fragments hoisted to registers; P aliases the Q smem buffer.
// ---------------------------------------------------------------------------
#define QSTR 68
#define VSTR 72

__global__ __launch_bounds__(128, 3)
void flash_tf32(const float* __restrict__ Q, const float* __restrict__ K,
                const float* __restrict__ V, float* __restrict__ O)
{
    extern __shared__ float sm[];
    float* Qs = sm;                       // [64][68] -> reused as Ps after Q hoist
    float* Ks = Qs + 64 * QSTR;           // [64][68]
    float* Vs = Ks + 64 * QSTR;           // [64][72]
    float* Ps = Qs;

    const int qb   = blockIdx.x;
    const int h    = blockIdx.y;
    const int b    = blockIdx.z;
    const int tid  = threadIdx.x;
    const int lane = tid & 31;
    const int warp = tid >> 5;
    const int q    = lane & 3;
    const int g    = lane >> 2;

    const float* Qg = Q + (((size_t)b * NH + h) * SEQ + qb * 64) * HD;
    const float* Kg = K + ((size_t)b * NKV + h / NREP) * SEQ * HD;
    const float* Vg = V + ((size_t)b * NKV + h / NREP) * SEQ * HD;

    // Load+convert Q tile to smem
#pragma unroll
    for (int i = 0; i < 8; i++) {
        int f = tid + 128 * i;
        int r = f >> 4;
        int c4 = (f & 15) << 2;
        float4 v = *(const float4*)&Qg[r * HD + c4];
        float4 w;
        w.x = tf32r(v.x); w.y = tf32r(v.y); w.z = tf32r(v.z); w.w = tf32r(v.w);
        *(float4*)&Qs[r * QSTR + c4] = w;
    }
    __syncthreads();

    const int rA = warp * 16 + g;

    // Hoist Q fragments into registers (Qs smem then becomes Ps)
    unsigned qf[8][4];
#pragma unroll
    for (int ks = 0; ks < 8; ks++) {
        const int k0 = ks * 8;
        qf[ks][0] = F2U(Qs[rA * QSTR + k0 + q]);
        qf[ks][1] = F2U(Qs[(rA + 8) * QSTR + k0 + q]);
        qf[ks][2] = F2U(Qs[rA * QSTR + k0 + 4 + q]);
        qf[ks][3] = F2U(Qs[(rA + 8) * QSTR + k0 + 4 + q]);
    }

    float m_i[2], l_i[2], o_acc[8][4];
#pragma unroll
    for (int rh = 0; rh < 2; rh++) { m_i[rh] = -INFINITY; l_i[rh] = 0.0f; }
#pragma unroll
    for (int nt = 0; nt < 8; nt++)
#pragma unroll
        for (int j = 0; j < 4; j++) o_acc[nt][j] = 0.0f;

    for (int kt = 0; kt <= qb; kt++) {
        // Load+convert K and V tiles
#pragma unroll
        for (int i = 0; i < 8; i++) {
            int f = tid + 128 * i;
            int r = f >> 4;
            int c4 = (f & 15) << 2;
            float4 kv = *(const float4*)&Kg[((size_t)kt * 64 + r) * HD + c4];
            float4 w;
            w.x = tf32r(kv.x); w.y = tf32r(kv.y); w.z = tf32r(kv.z); w.w = tf32r(kv.w);
            *(float4*)&Ks[r * QSTR + c4] = w;
            float4 vv = *(const float4*)&Vg[((size_t)kt * 64 + r) * HD + c4];
            w.x = tf32r(vv.x); w.y = tf32r(vv.y); w.z = tf32r(vv.z); w.w = tf32r(vv.w);
            *(float4*)&Vs[r * VSTR + c4] = w;
        }
        __syncthreads();

        // S = Q @ K^T
        float s_acc[8][4];
#pragma unroll
        for (int nt = 0; nt < 8; nt++)
#pragma unroll
            for (int j = 0; j < 4; j++) s_acc[nt][j] = 0.0f;

#pragma unroll
        for (int ks = 0; ks < 8; ks++) {
            const int k0 = ks * 8;
#pragma unroll
            for (int nt = 0; nt < 8; nt++) {
                const int n = nt * 8 + g;
                const unsigned b0 = F2U(Ks[n * QSTR + k0 + q]);
                const unsigned b1 = F2U(Ks[n * QSTR + k0 + 4 + q]);
                mma8(s_acc[nt], qf[ks][0], qf[ks][1], qf[ks][2], qf[ks][3], b0, b1);
            }
        }

        const bool diag = (kt == qb);

        // Online softmax per row-half
#pragma unroll
        for (int rh = 0; rh < 2; rh++) {
            const int rg = qb * 64 + rA + rh * 8;
            float mx = -INFINITY;
#pragma unroll
            for (int nt = 0; nt < 8; nt++) {
#pragma unroll
                for (int j = 0; j < 2; j++) {
                    float sv = s_acc[nt][rh * 2 + j] * 0.125f;
                    if (diag) {
                        int cg = kt * 64 + nt * 8 + (q << 1) + j;
                        if (cg > rg) sv = -INFINITY;
                    }
                    s_acc[nt][rh * 2 + j] = sv;
                    mx = fmaxf(mx, sv);
                }
            }
            mx = fmaxf(mx, __shfl_xor_sync(0xffffffffu, mx, 1));
            mx = fmaxf(mx, __shfl_xor_sync(0xffffffffu, mx, 2));

            const float mnew = fmaxf(m_i[rh], mx);
            const float sc = __expf(m_i[rh] - mnew);
            m_i[rh] = mnew;

            float rs = 0.0f;
#pragma unroll
            for (int nt = 0; nt < 8; nt++) {
#pragma unroll
                for (int j = 0; j < 2; j++) {
                    float p = __expf(s_acc[nt][rh * 2 + j] - mnew);
                    s_acc[nt][rh * 2 + j] = p;
                    rs += p;
                }
            }
            rs += __shfl_xor_sync(0xffffffffu, rs, 1);
            rs += __shfl_xor_sync(0xffffffffu, rs, 2);

            l_i[rh] = l_i[rh] * sc + rs;
#pragma unroll
            for (int nt = 0; nt < 8; nt++) {
                o_acc[nt][rh * 2]     *= sc;
                o_acc[nt][rh * 2 + 1] *= sc;
            }
        }

        // Stage P to smem (per-warp private rows)
#pragma unroll
        for (int nt = 0; nt < 8; nt++) {
            const int c = nt * 8 + (q << 1);
            Ps[rA * QSTR + c]           = tf32r(s_acc[nt][0]);
            Ps[rA * QSTR + c + 1]       = tf32r(s_acc[nt][1]);
            Ps[(rA + 8) * QSTR + c]     = tf32r(s_acc[nt][2]);
            Ps[(rA + 8) * QSTR + c + 1] = tf32r(s_acc[nt][3]);
        }
        __syncwarp();

        // O += P @ V
#pragma unroll
        for (int ks = 0; ks < 8; ks++) {
            const int k0 = ks * 8;
            const unsigned a0 = F2U(Ps[rA * QSTR + k0 + q]);
            const unsigned a1 = F2U(Ps[(rA + 8) * QSTR + k0 + q]);
            const unsigned a2 = F2U(Ps[rA * QSTR + k0 + 4 + q]);
            const unsigned a3 = F2U(Ps[(rA + 8) * QSTR + k0 + 4 + q]);
#pragma unroll
            for (int nt = 0; nt < 8; nt++) {
                const int n = nt * 8 + g;
                const unsigned b0 = F2U(Vs[(k0 + q) * VSTR + n]);
                const unsigned b1 = F2U(Vs[(k0 + 4 + q) * VSTR + n]);
                mma8(o_acc[nt], a0, a1, a2, a3, b0, b1);
            }
        }
        __syncthreads();
    }

    // Normalize, tf32-round (feeds gemm_o directly), write [b, s, h*HD]
    const float inv0 = 1.0f / l_i[0];
    const float inv1 = 1.0f / l_i[1];
#pragma unroll
    for (int nt = 0; nt < 8; nt++) {
        const int c = nt * 8 + (q << 1);
        const int r0 = qb * 64 + rA;
        float* p0 = O + ((size_t)b * SEQ + r0) * (NH * HD) + h * HD + c;
        p0[0] = tf32r(o_acc[nt][0] * inv0);
        p0[1] = tf32r(o_acc[nt][1] * inv0);
        float* p1 = O + ((size_t)b * SEQ + r0 + 8) * (NH * HD) + h * HD + c;
        p1[0] = tf32r(o_acc[nt][2] * inv1);
        p1[1] = tf32r(o_acc[nt][3] * inv1);
    }
}

// ---------------------------------------------------------------------------
// kernel_launch
// ---------------------------------------------------------------------------
extern "C" void kernel_launch(void* const* d_in, const int* in_sizes, int n_in,
                              void* d_out, int out_size)
{
    const float* hidden = (const float*)d_in[0];
    const float* wq = (const float*)d_in[1];
    const float* wk = (const float*)d_in[2];
    const float* wv = (const float*)d_in[3];
    const float* wo = (const float*)d_in[4];
    float* out = (float*)d_out;

    float *pq, *pk, *pv, *pattn, *pht, *pwqt, *pwkt, *pwvt, *pwot;
    cudaGetSymbolAddress((void**)&pq, g_q);
    cudaGetSymbolAddress((void**)&pk, g_k);
    cudaGetSymbolAddress((void**)&pv, g_v);
    cudaGetSymbolAddress((void**)&pattn, g_attn);
    cudaGetSymbolAddress((void**)&pht, g_ht);
    cudaGetSymbolAddress((void**)&pwqt, g_wqt);
    cudaGetSymbolAddress((void**)&pwkt, g_wkt);
    cudaGetSymbolAddress((void**)&pwvt, g_wvt);
    cudaGetSymbolAddress((void**)&pwot, g_wot);

    const int M = BSZ * SEQ;          // 4096

    // 1) tf32-round all GEMM inputs
    conv_tf32<<<(CUM5 + 255) / 256, 256>>>(hidden, wq, wk, wv, wo,
                                           pht, pwqt, pwkt, pwvt, pwot);

    // 2) fused QKV projection + RoPE (24 N-tiles: 16 Q, 4 K, 4 V)
    qkv_gemm<<<dim3(24, M / 128), dim3(256)>>>(pht);

    // 3) flash attention (tf32 tensor cores)
    size_t fsm = (size_t)(64 * QSTR * 2 + 64 * VSTR) * sizeof(float);
    cudaFuncSetAttribute(flash_tf32, cudaFuncAttributeMaxDynamicSharedMemorySize, (int)fsm);
    flash_tf32<<<dim3(SEQ / 64, NH, BSZ), dim3(128), fsm>>>(pq, pk, pv, pattn);

    // 4) output projection
    gemm_o<<<dim3(HIDDEN / 128, M / 128), dim3(256)>>>(pattn, pwot, out);
}

// round 5
// speedup vs baseline: 4.0971x; 1.1823x over previous
#include <cuda_runtime.h>
#include <math.h>
#include <stdint.h>

#define BSZ 2
#define SEQ 2048
#define HIDDEN 2048
#define NH 32
#define NKV 8
#define HD 64
#define NREP 4

// Scratch (static device arrays — no allocation).
__device__ float g_q[BSZ * NH * SEQ * HD];      // [b, h, s, d] tf32-rounded, pre-scaled 1/8
__device__ float g_k[BSZ * NKV * SEQ * HD];     // [b, kvh, s, d] tf32-rounded
__device__ float g_v[BSZ * NKV * SEQ * HD];     // [b, kvh, s, d] tf32-rounded
__device__ float g_attn[BSZ * SEQ * NH * HD];   // [b, s, h*d] tf32-rounded

// tf32-rounded copies of the GEMM inputs.
__device__ float g_ht[BSZ * SEQ * HIDDEN];
__device__ float g_wqt[HIDDEN * NH * HD];
__device__ float g_wkt[HIDDEN * NKV * HD];
__device__ float g_wvt[HIDDEN * NKV * HD];
__device__ float g_wot[NH * HD * HIDDEN];

// ---------------------------------------------------------------------------
// Helpers
// ---------------------------------------------------------------------------
__device__ __forceinline__ float tf32r(float x) {
    unsigned u;
    asm("cvt.rna.tf32.f32 %0, %1;" : "=r"(u) : "f"(x));
    return __uint_as_float(u);
}

__device__ __forceinline__ void mma8(float c[4],
                                     unsigned a0, unsigned a1, unsigned a2, unsigned a3,
                                     unsigned b0, unsigned b1) {
    asm volatile(
        "mma.sync.aligned.m16n8k8.row.col.f32.tf32.tf32.f32 "
        "{%0,%1,%2,%3}, {%4,%5,%6,%7}, {%8,%9}, {%0,%1,%2,%3};\n"
        : "+f"(c[0]), "+f"(c[1]), "+f"(c[2]), "+f"(c[3])
        : "r"(a0), "r"(a1), "r"(a2), "r"(a3), "r"(b0), "r"(b1));
}

__device__ __forceinline__ void ldsm4(unsigned& r0, unsigned& r1,
                                      unsigned& r2, unsigned& r3, uint32_t addr) {
    asm volatile("ldmatrix.sync.aligned.m8n8.x4.shared.b16 {%0,%1,%2,%3}, [%4];"
                 : "=r"(r0), "=r"(r1), "=r"(r2), "=r"(r3) : "r"(addr));
}
__device__ __forceinline__ void ldsm2(unsigned& r0, unsigned& r1, uint32_t addr) {
    asm volatile("ldmatrix.sync.aligned.m8n8.x2.shared.b16 {%0,%1}, [%2];"
                 : "=r"(r0), "=r"(r1) : "r"(addr));
}
#define F2U __float_as_uint

// ---------------------------------------------------------------------------
// Prologue: round hidden + weights to tf32
// ---------------------------------------------------------------------------
#define N_H4  (BSZ * SEQ * HIDDEN / 4)
#define N_WQ4 (HIDDEN * NH * HD / 4)
#define N_WK4 (HIDDEN * NKV * HD / 4)
#define CUM1 N_H4
#define CUM2 (CUM1 + N_WQ4)
#define CUM3 (CUM2 + N_WK4)
#define CUM4 (CUM3 + N_WK4)
#define CUM5 (CUM4 + N_WQ4)

__global__ void conv_tf32(const float* __restrict__ h, const float* __restrict__ wq,
                          const float* __restrict__ wk, const float* __restrict__ wv,
                          const float* __restrict__ wo,
                          float* __restrict__ ht, float* __restrict__ wqt,
                          float* __restrict__ wkt, float* __restrict__ wvt,
                          float* __restrict__ wot)
{
    int i = blockIdx.x * blockDim.x + threadIdx.x;
    if (i >= CUM5) return;
    const float4* s;
    float4* d;
    if (i < CUM1)      { s = (const float4*)h  + i;          d = (float4*)ht  + i; }
    else if (i < CUM2) { s = (const float4*)wq + (i - CUM1); d = (float4*)wqt + (i - CUM1); }
    else if (i < CUM3) { s = (const float4*)wk + (i - CUM2); d = (float4*)wkt + (i - CUM2); }
    else if (i < CUM4) { s = (const float4*)wv + (i - CUM3); d = (float4*)wvt + (i - CUM3); }
    else               { s = (const float4*)wo + (i - CUM4); d = (float4*)wot + (i - CUM4); }
    float4 v = *s;
    v.x = tf32r(v.x); v.y = tf32r(v.y); v.z = tf32r(v.z); v.w = tf32r(v.w);
    *d = v;
}

// ---------------------------------------------------------------------------
// GEMM mainloop: 128x128 tile, BK=16, 256 thr (8 warps), 3-stage cp.async.
// WARPS_M x WARPS_N warp grid; warp tile (MT*16) x (NT*8).
// A fragments via ldmatrix; B fragments scalar LDS (k-major smem).
// ---------------------------------------------------------------------------
#define ASTR 20
#define BSTR 136
#define A_STAGE (128 * ASTR)   // floats
#define B_STAGE (16 * BSTR)    // floats
#define GEMM_SMEM (3 * (A_STAGE + B_STAGE) * 4)

template<int WARPS_M>
__device__ __forceinline__ void gemm_mainloop(
    const float* __restrict__ Ag, const float* __restrict__ Bg,
    int K, int N, float (*acc)[4])
{
    extern __shared__ float smem[];
    float* As = smem;
    float* Bs = smem + 3 * A_STAGE;

    constexpr int MT = 8 / WARPS_M;
    constexpr int NT = 2 * WARPS_M;

    const int tid  = threadIdx.x;
    const int lane = tid & 31;
    const int warp = tid >> 5;
    const int wm   = warp % WARPS_M;
    const int wn   = warp / WARPS_M;
    const int q    = lane & 3;
    const int g    = lane >> 2;

    const int ar = tid >> 2;
    const int ac = (tid & 3) << 2;
    const int bk = tid >> 5;
    const int bn = (tid & 31) << 2;

    const uint32_t sA = (uint32_t)__cvta_generic_to_shared(As);
    const uint32_t sB = (uint32_t)__cvta_generic_to_shared(Bs);

    const int arow = ((lane >> 3) & 1) * 8 + (lane & 7);
    const int acol = (lane >> 4) * 4;
    const uint32_t abase = sA + (uint32_t)(((wm * MT * 16 + arow) * ASTR + acol) * 4);

#define ISSUE(kb, st) do {                                                          \
    const float* a0 = Ag + (size_t)ar * K + (kb) * 16 + ac;                         \
    uint32_t da = sA + (uint32_t)(((st) * A_STAGE + ar * ASTR + ac) * 4);           \
    asm volatile("cp.async.cg.shared.global [%0], [%1], 16;" :: "r"(da), "l"(a0));  \
    asm volatile("cp.async.cg.shared.global [%0], [%1], 16;"                        \
                 :: "r"(da + 64u * ASTR * 4u), "l"(a0 + (size_t)64 * K));           \
    const float* b0p = Bg + (size_t)((kb) * 16 + bk) * N + bn;                      \
    uint32_t db = sB + (uint32_t)(((st) * B_STAGE + bk * BSTR + bn) * 4);           \
    asm volatile("cp.async.cg.shared.global [%0], [%1], 16;" :: "r"(db), "l"(b0p)); \
    asm volatile("cp.async.cg.shared.global [%0], [%1], 16;"                        \
                 :: "r"(db + 8u * BSTR * 4u), "l"(b0p + (size_t)8 * N));            \
    asm volatile("cp.async.commit_group;");                                         \
} while (0)

    const int nkb = K >> 4;
    ISSUE(0, 0);
    ISSUE(1, 1);

    for (int kb = 0; kb < nkb; kb++) {
        if (kb < nkb - 1) asm volatile("cp.async.wait_group 1;");
        else              asm volatile("cp.async.wait_group 0;");
        __syncthreads();

        const int st = kb % 3;
        const float* B0 = Bs + st * B_STAGE;
        const uint32_t aS = abase + (uint32_t)(st * A_STAGE * 4);

#pragma unroll
        for (int ks = 0; ks < 2; ks++) {
            const int k0 = ks * 8;
            unsigned a[MT][4];
#pragma unroll
            for (int mt = 0; mt < MT; mt++)
                ldsm4(a[mt][0], a[mt][1], a[mt][2], a[mt][3],
                      aS + (uint32_t)((mt * 16 * ASTR + k0) * 4));
#pragma unroll
            for (int nt = 0; nt < NT; nt++) {
                const int n = wn * (NT * 8) + nt * 8 + g;
                const unsigned b0 = F2U(B0[(k0 + q) * BSTR + n]);
                const unsigned b1 = F2U(B0[(k0 + 4 + q) * BSTR + n]);
#pragma unroll
                for (int mt = 0; mt < MT; mt++)
                    mma8(acc[mt * NT + nt], a[mt][0], a[mt][1], a[mt][2], a[mt][3], b0, b1);
            }
        }
        if (kb + 2 < nkb) ISSUE(kb + 2, (kb + 2) % 3);
    }
#undef ISSUE
}

// ---------------------------------------------------------------------------
// Fused QKV projection + RoPE epilogue (tf32-rounded outputs; Q pre-scaled 1/8)
// grid.x = 24: bx<16 -> Q, bx<20 -> K, else V. WARPS_M=4: warp tile 32x64.
// ---------------------------------------------------------------------------
__global__ __launch_bounds__(256, 2)
void qkv_gemm(const float* __restrict__ hidden)
{
    const int bx = blockIdx.x, by = blockIdx.y;
    const int tid = threadIdx.x;
    const int lane = tid & 31, warp = tid >> 5;
    const int wm = warp % 4, wn = warp / 4;
    const int q = lane & 3, g = lane >> 2;

    const float* W;
    float* Out;
    int N, cb, heads;
    bool rope;
    float oscale;
    if (bx < 16)      { W = g_wqt; Out = g_q; N = NH * HD;  cb = bx * 128;        heads = NH;  rope = true;  oscale = 0.125f; }
    else if (bx < 20) { W = g_wkt; Out = g_k; N = NKV * HD; cb = (bx - 16) * 128; heads = NKV; rope = true;  oscale = 1.0f; }
    else              { W = g_wvt; Out = g_v; N = NKV * HD; cb = (bx - 20) * 128; heads = NKV; rope = false; oscale = 1.0f; }

    float acc[16][4];
#pragma unroll
    for (int i = 0; i < 16; i++)
#pragma unroll
        for (int j = 0; j < 4; j++) acc[i][j] = 0.0f;

    gemm_mainloop<4>(hidden + (size_t)(by * 128) * HIDDEN, W + cb, HIDDEN, N, acc);

    // RoPE in registers: pair (nt, nt+4) holds head-dims (d, d+32)
    if (rope) {
        float invf[8];
#pragma unroll
        for (int ntp = 0; ntp < 4; ntp++)
#pragma unroll
            for (int j = 0; j < 2; j++)
                invf[ntp * 2 + j] =
                    powf(10000.0f, -((float)(2 * (ntp * 8 + (q << 1) + j)) / 64.0f));
#pragma unroll
        for (int mt = 0; mt < 2; mt++) {
#pragma unroll
            for (int rh = 0; rh < 2; rh++) {
                const int m = by * 128 + wm * 32 + mt * 16 + g + rh * 8;
                const float s = (float)(m & (SEQ - 1));
#pragma unroll
                for (int ntp = 0; ntp < 4; ntp++) {
#pragma unroll
                    for (int j = 0; j < 2; j++) {
                        float c, si;
                        sincosf(s * invf[ntp * 2 + j], &si, &c);
                        const float x1 = acc[mt * 8 + ntp][rh * 2 + j];
                        const float x2 = acc[mt * 8 + ntp + 4][rh * 2 + j];
                        acc[mt * 8 + ntp][rh * 2 + j]     = x1 * c - x2 * si;
                        acc[mt * 8 + ntp + 4][rh * 2 + j] = x2 * c + x1 * si;
                    }
                }
            }
        }
    }

    // Scatter store to [b, h, s, d], tf32-rounded (+pre-scale for Q)
#pragma unroll
    for (int mt = 0; mt < 2; mt++) {
        const int row = by * 128 + wm * 32 + mt * 16 + g;
#pragma unroll
        for (int nt = 0; nt < 8; nt++) {
            const int col = cb + wn * 64 + nt * 8 + (q << 1);
            const int hh = col / HD, dd = col & (HD - 1);
#pragma unroll
            for (int rh = 0; rh < 2; rh++) {
                const int m = row + rh * 8;
                const int bb = m >> 11, ss = m & (SEQ - 1);
                float* p = Out + (((size_t)bb * heads + hh) * SEQ + ss) * HD + dd;
                p[0] = tf32r(acc[mt * 8 + nt][rh * 2]     * oscale);
                p[1] = tf32r(acc[mt * 8 + nt][rh * 2 + 1] * oscale);
            }
        }
    }
}

// ---------------------------------------------------------------------------
// Output projection: WARPS_M=2 (warp tile 64x32, max B-fragment reuse)
// ---------------------------------------------------------------------------
__global__ __launch_bounds__(256, 2)
void gemm_o(const float* __restrict__ A, const float* __restrict__ B,
            float* __restrict__ C)
{
    const int bx = blockIdx.x, by = blockIdx.y;
    const int tid = threadIdx.x;
    const int lane = tid & 31, warp = tid >> 5;
    const int wm = warp % 2, wn = warp / 2;
    const int q = lane & 3, g = lane >> 2;
    const int N = HIDDEN;

    float acc[16][4];
#pragma unroll
    for (int i = 0; i < 16; i++)
#pragma unroll
        for (int j = 0; j < 4; j++) acc[i][j] = 0.0f;

    gemm_mainloop<2>(A + (size_t)(by * 128) * HIDDEN, B + bx * 128, HIDDEN, N, acc);

#pragma unroll
    for (int mt = 0; mt < 4; mt++) {
        const int row = by * 128 + wm * 64 + mt * 16 + g;
#pragma unroll
        for (int nt = 0; nt < 4; nt++) {
            const int col = bx * 128 + wn * 32 + nt * 8 + (q << 1);
            *(float2*)(C + (size_t)row * N + col) =
                make_float2(acc[mt * 4 + nt][0], acc[mt * 4 + nt][1]);
            *(float2*)(C + (size_t)(row + 8) * N + col) =
                make_float2(acc[mt * 4 + nt][2], acc[mt * 4 + nt][3]);
        }
    }
}

// ---------------------------------------------------------------------------
// Flash attention, tf32 mma, causal. 64-row Q tiles, 4 warps, occ 3.
// Inputs pre-rounded & Q pre-scaled. cp.async K/V alternating pipeline.
// K and P fragments via ldmatrix; V scalar. Ps aliases Qs.
// ---------------------------------------------------------------------------
#define QSTR 68
#define VSTR 72
#define FLASH_SMEM ((64 * QSTR * 2 + 64 * VSTR) * 4)

__global__ __launch_bounds__(128, 3)
void flash_tf32(const float* __restrict__ Q, const float* __restrict__ K,
                const float* __restrict__ V, float* __restrict__ O)
{
    extern __shared__ float sm[];
    float* Qs = sm;                       // [64][68] -> reused as Ps after hoist
    float* Ks = Qs + 64 * QSTR;           // [64][68]
    float* Vs = Ks + 64 * QSTR;           // [64][72]
    float* Ps = Qs;

    const int qb   = blockIdx.x;
    const int h    = blockIdx.y;
    const int b    = blockIdx.z;
    const int tid  = threadIdx.x;
    const int lane = tid & 31;
    const int warp = tid >> 5;
    const int q    = lane & 3;
    const int g    = lane >> 2;

    const float* Qg = Q + (((size_t)b * NH + h) * SEQ + qb * 64) * HD;
    const float* Kg = K + ((size_t)b * NKV + h / NREP) * SEQ * HD;
    const float* Vg = V + ((size_t)b * NKV + h / NREP) * SEQ * HD;

    const uint32_t sKs = (uint32_t)__cvta_generic_to_shared(Ks);
    const uint32_t sVs = (uint32_t)__cvta_generic_to_shared(Vs);
    const uint32_t sPs = (uint32_t)__cvta_generic_to_shared(Ps);

    auto issue_k = [&](int kt) {
#pragma unroll
        for (int i = 0; i < 8; i++) {
            const int f = tid + 128 * i;
            const int r = f >> 4, c4 = (f & 15) << 2;
            const uint32_t d = sKs + (uint32_t)((r * QSTR + c4) * 4);
            const float* s = Kg + (size_t)kt * 64 * HD + f * 4;
            asm volatile("cp.async.cg.shared.global [%0], [%1], 16;" :: "r"(d), "l"(s));
        }
        asm volatile("cp.async.commit_group;");
    };
    auto issue_v = [&](int kt) {
#pragma unroll
        for (int i = 0; i < 8; i++) {
            const int f = tid + 128 * i;
            const int r = f >> 4, c4 = (f & 15) << 2;
            const uint32_t d = sVs + (uint32_t)((r * VSTR + c4) * 4);
            const float* s = Vg + (size_t)kt * 64 * HD + f * 4;
            asm volatile("cp.async.cg.shared.global [%0], [%1], 16;" :: "r"(d), "l"(s));
        }
        asm volatile("cp.async.commit_group;");
    };

    // Prologue: start K0/V0 while loading Q
    issue_k(0);
    issue_v(0);

#pragma unroll
    for (int i = 0; i < 8; i++) {
        const int f = tid + 128 * i;
        const int r = f >> 4, c4 = (f & 15) << 2;
        *(float4*)&Qs[r * QSTR + c4] = *(const float4*)&Qg[r * HD + c4];
    }
    __syncthreads();

    const int rA = warp * 16 + g;

    // Hoist Q fragments (Qs then becomes Ps)
    unsigned qf[8][4];
#pragma unroll
    for (int ks = 0; ks < 8; ks++) {
        const int k0 = ks * 8;
        qf[ks][0] = F2U(Qs[rA * QSTR + k0 + q]);
        qf[ks][1] = F2U(Qs[(rA + 8) * QSTR + k0 + q]);
        qf[ks][2] = F2U(Qs[rA * QSTR + k0 + 4 + q]);
        qf[ks][3] = F2U(Qs[(rA + 8) * QSTR + k0 + 4 + q]);
    }

    // ldmatrix per-thread address components
    const int arow = ((lane >> 3) & 1) * 8 + (lane & 7);
    const int acol = (lane >> 4) * 4;
    const uint32_t pbase = sPs + (uint32_t)(((warp * 16 + arow) * QSTR + acol) * 4);
    const uint32_t kfbase = sKs + (uint32_t)(((lane & 7) * QSTR + ((lane >> 3) & 1) * 4) * 4);

    float m_i[2], l_i[2], o_acc[8][4];
#pragma unroll
    for (int rh = 0; rh < 2; rh++) { m_i[rh] = -INFINITY; l_i[rh] = 0.0f; }
#pragma unroll
    for (int nt = 0; nt < 8; nt++)
#pragma unroll
        for (int j = 0; j < 4; j++) o_acc[nt][j] = 0.0f;

    for (int kt = 0; kt <= qb; kt++) {
        // K(kt) ready (V(kt) may still be in flight)
        asm volatile("cp.async.wait_group 1;");
        __syncthreads();

        // S = Q @ K^T
        float s_acc[8][4];
#pragma unroll
        for (int nt = 0; nt < 8; nt++)
#pragma unroll
            for (int j = 0; j < 4; j++) s_acc[nt][j] = 0.0f;

#pragma unroll
        for (int ks = 0; ks < 8; ks++) {
#pragma unroll
            for (int nt = 0; nt < 8; nt++) {
                unsigned b0, b1;
                ldsm2(b0, b1, kfbase + (uint32_t)((nt * 8 * QSTR + ks * 8) * 4));
                mma8(s_acc[nt], qf[ks][0], qf[ks][1], qf[ks][2], qf[ks][3], b0, b1);
            }
        }

        const bool diag = (kt == qb);

        // Online softmax per row-half (Q pre-scaled, no 1/8 here)
#pragma unroll
        for (int rh = 0; rh < 2; rh++) {
            const int rg = qb * 64 + rA + rh * 8;
            float mx = -INFINITY;
#pragma unroll
            for (int nt = 0; nt < 8; nt++) {
#pragma unroll
                for (int j = 0; j < 2; j++) {
                    float sv = s_acc[nt][rh * 2 + j];
                    if (diag) {
                        int cg = kt * 64 + nt * 8 + (q << 1) + j;
                        if (cg > rg) sv = -INFINITY;
                    }
                    s_acc[nt][rh * 2 + j] = sv;
                    mx = fmaxf(mx, sv);
                }
            }
            mx = fmaxf(mx, __shfl_xor_sync(0xffffffffu, mx, 1));
            mx = fmaxf(mx, __shfl_xor_sync(0xffffffffu, mx, 2));

            const float mnew = fmaxf(m_i[rh], mx);
            const float sc = __expf(m_i[rh] - mnew);
            m_i[rh] = mnew;

            float rs = 0.0f;
#pragma unroll
            for (int nt = 0; nt < 8; nt++) {
#pragma unroll
                for (int j = 0; j < 2; j++) {
                    float p = __expf(s_acc[nt][rh * 2 + j] - mnew);
                    s_acc[nt][rh * 2 + j] = p;
                    rs += p;
                }
            }
            rs += __shfl_xor_sync(0xffffffffu, rs, 1);
            rs += __shfl_xor_sync(0xffffffffu, rs, 2);

            l_i[rh] = l_i[rh] * sc + rs;
#pragma unroll
            for (int nt = 0; nt < 8; nt++) {
                o_acc[nt][rh * 2]     *= sc;
                o_acc[nt][rh * 2 + 1] *= sc;
            }
        }

        // Stage P to smem (warp-private rows)
#pragma unroll
        for (int nt = 0; nt < 8; nt++) {
            const int c = nt * 8 + (q << 1);
            Ps[rA * QSTR + c]           = tf32r(s_acc[nt][0]);
            Ps[rA * QSTR + c + 1]       = tf32r(s_acc[nt][1]);
            Ps[(rA + 8) * QSTR + c]     = tf32r(s_acc[nt][2]);
            Ps[(rA + 8) * QSTR + c + 1] = tf32r(s_acc[nt][3]);
        }
        __syncwarp();

        // V(kt) ready; barrier also closes all warps' S-phase reads of Ks
        asm volatile("cp.async.wait_group 0;");
        __syncthreads();
        if (kt < qb) issue_k(kt + 1);

        // O += P @ V
#pragma unroll
        for (int ks = 0; ks < 8; ks++) {
            const int k0 = ks * 8;
            unsigned a0, a1, a2, a3;
            ldsm4(a0, a1, a2, a3, pbase + (uint32_t)(k0 * 4));
#pragma unroll
            for (int nt = 0; nt < 8; nt++) {
                const int n = nt * 8 + g;
                const unsigned b0 = F2U(Vs[(k0 + q) * VSTR + n]);
                const unsigned b1 = F2U(Vs[(k0 + 4 + q) * VSTR + n]);
                mma8(o_acc[nt], a0, a1, a2, a3, b0, b1);
            }
        }
        __syncthreads();
        if (kt < qb) issue_v(kt + 1);
    }

    // Normalize, tf32-round (feeds gemm_o), write [b, s, h*HD]
    const float inv0 = 1.0f / l_i[0];
    const float inv1 = 1.0f / l_i[1];
#pragma unroll
    for (int nt = 0; nt < 8; nt++) {
        const int c = nt * 8 + (q << 1);
        const int r0 = qb * 64 + rA;
        float* p0 = O + ((size_t)b * SEQ + r0) * (NH * HD) + h * HD + c;
        p0[0] = tf32r(o_acc[nt][0] * inv0);
        p0[1] = tf32r(o_acc[nt][1] * inv0);
        float* p1 = O + ((size_t)b * SEQ + r0 + 8) * (NH * HD) + h * HD + c;
        p1[0] = tf32r(o_acc[nt][2] * inv1);
        p1[1] = tf32r(o_acc[nt][3] * inv1);
    }
}

// ---------------------------------------------------------------------------
// kernel_launch
// ---------------------------------------------------------------------------
extern "C" void kernel_launch(void* const* d_in, const int* in_sizes, int n_in,
                              void* d_out, int out_size)
{
    const float* hidden = (const float*)d_in[0];
    const float* wq = (const float*)d_in[1];
    const float* wk = (const float*)d_in[2];
    const float* wv = (const float*)d_in[3];
    const float* wo = (const float*)d_in[4];
    float* out = (float*)d_out;

    float *pq, *pk, *pv, *pattn, *pht, *pwqt, *pwkt, *pwvt, *pwot;
    cudaGetSymbolAddress((void**)&pq, g_q);
    cudaGetSymbolAddress((void**)&pk, g_k);
    cudaGetSymbolAddress((void**)&pv, g_v);
    cudaGetSymbolAddress((void**)&pattn, g_attn);
    cudaGetSymbolAddress((void**)&pht, g_ht);
    cudaGetSymbolAddress((void**)&pwqt, g_wqt);
    cudaGetSymbolAddress((void**)&pwkt, g_wkt);
    cudaGetSymbolAddress((void**)&pwvt, g_wvt);
    cudaGetSymbolAddress((void**)&pwot, g_wot);

    const int M = BSZ * SEQ;          // 4096

    cudaFuncSetAttribute(qkv_gemm, cudaFuncAttributeMaxDynamicSharedMemorySize, GEMM_SMEM);
    cudaFuncSetAttribute(gemm_o, cudaFuncAttributeMaxDynamicSharedMemorySize, GEMM_SMEM);
    cudaFuncSetAttribute(flash_tf32, cudaFuncAttributeMaxDynamicSharedMemorySize, FLASH_SMEM);

    // 1) tf32-round all GEMM inputs
    conv_tf32<<<(CUM5 + 255) / 256, 256>>>(hidden, wq, wk, wv, wo,
                                           pht, pwqt, pwkt, pwvt, pwot);

    // 2) fused QKV projection + RoPE (24 N-tiles: 16 Q, 4 K, 4 V)
    qkv_gemm<<<dim3(24, M / 128), dim3(256), GEMM_SMEM>>>(pht);

    // 3) flash attention
    flash_tf32<<<dim3(SEQ / 64, NH, BSZ), dim3(128), FLASH_SMEM>>>(pq, pk, pv, pattn);

    // 4) output projection
    gemm_o<<<dim3(HIDDEN / 128, M / 128), dim3(256), GEMM_SMEM>>>(pattn, pwot, out);
}

// round 7
// speedup vs baseline: 4.1051x; 1.0020x over previous
#include <cuda_runtime.h>
#include <math.h>
#include <stdint.h>

#define BSZ 2
#define SEQ 2048
#define HIDDEN 2048
#define NH 32
#define NKV 8
#define HD 64
#define NREP 4

// Scratch (static device arrays — no allocation).
__device__ float g_q[BSZ * NH * SEQ * HD];      // [b, h, s, d] tf32-rounded, pre-scaled 1/8
__device__ float g_k[BSZ * NKV * SEQ * HD];     // [b, kvh, s, d] tf32-rounded
__device__ float g_v[BSZ * NKV * SEQ * HD];     // [b, kvh, s, d] tf32-rounded
__device__ float g_attn[BSZ * SEQ * NH * HD];   // [b, s, h*d] tf32-rounded

__device__ float g_ht[BSZ * SEQ * HIDDEN];      // tf32-rounded hidden
__device__ float g_wqt[NH * HD * HIDDEN];       // [N,K] k-major, tf32-rounded
__device__ float g_wkt[NKV * HD * HIDDEN];
__device__ float g_wvt[NKV * HD * HIDDEN];
__device__ float g_wot[HIDDEN * NH * HD];       // [N=2048, K=2048]

// ---------------------------------------------------------------------------
// Helpers
// ---------------------------------------------------------------------------
__device__ __forceinline__ float tf32r(float x) {
    unsigned u;
    asm("cvt.rna.tf32.f32 %0, %1;" : "=r"(u) : "f"(x));
    return __uint_as_float(u);
}
#define F2U __float_as_uint

__device__ __forceinline__ void mma8(float c[4],
                                     unsigned a0, unsigned a1, unsigned a2, unsigned a3,
                                     unsigned b0, unsigned b1) {
    asm volatile(
        "mma.sync.aligned.m16n8k8.row.col.f32.tf32.tf32.f32 "
        "{%0,%1,%2,%3}, {%4,%5,%6,%7}, {%8,%9}, {%0,%1,%2,%3};\n"
        : "+f"(c[0]), "+f"(c[1]), "+f"(c[2]), "+f"(c[3])
        : "r"(a0), "r"(a1), "r"(a2), "r"(a3), "r"(b0), "r"(b1));
}
__device__ __forceinline__ void ldsm4(unsigned& r0, unsigned& r1,
                                      unsigned& r2, unsigned& r3, uint32_t addr) {
    asm volatile("ldmatrix.sync.aligned.m8n8.x4.shared.b16 {%0,%1,%2,%3}, [%4];"
                 : "=r"(r0), "=r"(r1), "=r"(r2), "=r"(r3) : "r"(addr));
}

// ---------------------------------------------------------------------------
// Prologue kernels: elementwise round; tiled transpose+round
// ---------------------------------------------------------------------------
__global__ void round_tf32(const float* __restrict__ src, float* __restrict__ dst, int n4)
{
    int i = blockIdx.x * blockDim.x + threadIdx.x;
    if (i >= n4) return;
    float4 v = ((const float4*)src)[i];
    v.x = tf32r(v.x); v.y = tf32r(v.y); v.z = tf32r(v.z); v.w = tf32r(v.w);
    ((float4*)dst)[i] = v;
}

// dst[n*Kd + k] = tf32r(src[k*Nd + n])
__global__ void transpose_tf32(const float* __restrict__ src, float* __restrict__ dst,
                               int Kd, int Nd)
{
    __shared__ float t[32][33];
    const int n0 = blockIdx.x * 32, k0 = blockIdx.y * 32;
    const int tx = threadIdx.x, ty = threadIdx.y;
#pragma unroll
    for (int i = 0; i < 4; i++)
        t[ty + i * 8][tx] = src[(size_t)(k0 + ty + i * 8) * Nd + n0 + tx];
    __syncthreads();
#pragma unroll
    for (int i = 0; i < 4; i++)
        dst[(size_t)(n0 + ty + i * 8) * Kd + k0 + tx] = tf32r(t[tx][ty + i * 8]);
}

// ---------------------------------------------------------------------------
// GEMM mainloop v2: 128x128 tile, BK=16, 256 thr (8 warps), 3-stage cp.async.
// A [128 m-rows, K] k-major; B [128 n-rows, K] k-major (weights pre-transposed).
// Both fragment types via ldmatrix. Warp grid WARPS_M x (8/WARPS_M);
// warp tile (MT*16)m x (NT*8)n, MT = 8/WARPS_M, NT = 2*WARPS_M.
// ---------------------------------------------------------------------------
#define ASTR 20
#define STAGE_F (128 * ASTR)                 // floats per (A or B) stage
#define GEMM_SMEM (3 * 2 * STAGE_F * 4)      // 61440 bytes

template<int WARPS_M>
__device__ __forceinline__ void gemm_mainloop2(
    const float* __restrict__ Ag, const float* __restrict__ Bg,
    int K, float (*acc)[4])
{
    extern __shared__ float smem[];
    float* As = smem;
    float* Bs = smem + 3 * STAGE_F;

    constexpr int MT = 8 / WARPS_M;
    constexpr int NT = 2 * WARPS_M;
    constexpr int NPAIR = NT / 2;

    const int tid  = threadIdx.x;
    const int lane = tid & 31;
    const int warp = tid >> 5;
    const int wm   = warp % WARPS_M;
    const int wn   = warp / WARPS_M;

    const int gr = tid >> 2;           // load row (second chunk +64)
    const int gc = (tid & 3) << 2;     // load k-col (float4)

    const uint32_t sA = (uint32_t)__cvta_generic_to_shared(As);
    const uint32_t sB = (uint32_t)__cvta_generic_to_shared(Bs);

    // ldmatrix base addresses
    const int frow = ((lane >> 3) & 1) * 8 + (lane & 7);     // A: mat0/1 rows, mat2/3 col+4
    const int fcol = (lane >> 4) * 4;
    const uint32_t abase = sA + (uint32_t)(((wm * MT * 16 + frow) * ASTR + fcol) * 4);
    const int brow = (lane & 7) + ((lane >> 4) & 1) * 8;     // B: mat0/1 = n0-7 k0/k4, mat2/3 = n8-15
    const int bcol = ((lane >> 3) & 1) * 4;
    const uint32_t bbase = sB + (uint32_t)(((wn * NT * 8 + brow) * ASTR + bcol) * 4);

#define ISSUE(kb, st) do {                                                          \
    const float* a0 = Ag + (size_t)gr * K + (kb) * 16 + gc;                         \
    uint32_t da = sA + (uint32_t)(((st) * STAGE_F + gr * ASTR + gc) * 4);           \
    asm volatile("cp.async.cg.shared.global [%0], [%1], 16;" :: "r"(da), "l"(a0));  \
    asm volatile("cp.async.cg.shared.global [%0], [%1], 16;"                        \
                 :: "r"(da + 64u * ASTR * 4u), "l"(a0 + (size_t)64 * K));           \
    const float* b0p = Bg + (size_t)gr * K + (kb) * 16 + gc;                        \
    uint32_t db = sB + (uint32_t)(((st) * STAGE_F + gr * ASTR + gc) * 4);           \
    asm volatile("cp.async.cg.shared.global [%0], [%1], 16;" :: "r"(db), "l"(b0p)); \
    asm volatile("cp.async.cg.shared.global [%0], [%1], 16;"                        \
                 :: "r"(db + 64u * ASTR * 4u), "l"(b0p + (size_t)64 * K));          \
    asm volatile("cp.async.commit_group;");                                         \
} while (0)

    const int nkb = K >> 4;
    ISSUE(0, 0);
    ISSUE(1, 1);

    for (int kb = 0; kb < nkb; kb++) {
        if (kb < nkb - 1) asm volatile("cp.async.wait_group 1;");
        else              asm volatile("cp.async.wait_group 0;");
        __syncthreads();

        const int st = kb % 3;
        const uint32_t aS = abase + (uint32_t)(st * STAGE_F * 4);
        const uint32_t bS = bbase + (uint32_t)(st * STAGE_F * 4);

#pragma unroll
        for (int ks = 0; ks < 2; ks++) {
            const int k0 = ks * 8;
            unsigned a[MT][4];
#pragma unroll
            for (int mt = 0; mt < MT; mt++)
                ldsm4(a[mt][0], a[mt][1], a[mt][2], a[mt][3],
                      aS + (uint32_t)((mt * 16 * ASTR + k0) * 4));
#pragma unroll
            for (int ntp = 0; ntp < NPAIR; ntp++) {
                unsigned b0, b1, b2, b3;
                ldsm4(b0, b1, b2, b3, bS + (uint32_t)((ntp * 16 * ASTR + k0) * 4));
#pragma unroll
                for (int mt = 0; mt < MT; mt++) {
                    mma8(acc[mt * NT + 2 * ntp],     a[mt][0], a[mt][1], a[mt][2], a[mt][3], b0, b1);
                    mma8(acc[mt * NT + 2 * ntp + 1], a[mt][0], a[mt][1], a[mt][2], a[mt][3], b2, b3);
                }
            }
        }
        if (kb + 2 < nkb) ISSUE(kb + 2, (kb + 2) % 3);
    }
#undef ISSUE
}

// ---------------------------------------------------------------------------
// Fused QKV projection + RoPE epilogue. WARPS_M=4 (warp tile 32x64; RoPE
// pairs (d, d+32) stay in-warp as nt, nt+4).
// grid.x = 24: bx<16 -> Q, bx<20 -> K, else V.
// ---------------------------------------------------------------------------
__global__ __launch_bounds__(256, 2)
void qkv_gemm()
{
    const int bx = blockIdx.x, by = blockIdx.y;
    const int tid = threadIdx.x;
    const int lane = tid & 31, warp = tid >> 5;
    const int wm = warp % 4, wn = warp / 4;
    const int q = lane & 3, g = lane >> 2;

    const float* W;
    float* Out;
    int cb, heads;
    bool rope;
    float oscale;
    if (bx < 16)      { W = g_wqt; Out = g_q; cb = bx * 128;        heads = NH;  rope = true;  oscale = 0.125f; }
    else if (bx < 20) { W = g_wkt; Out = g_k; cb = (bx - 16) * 128; heads = NKV; rope = true;  oscale = 1.0f; }
    else              { W = g_wvt; Out = g_v; cb = (bx - 20) * 128; heads = NKV; rope = false; oscale = 1.0f; }

    float acc[16][4];
#pragma unroll
    for (int i = 0; i < 16; i++)
#pragma unroll
        for (int j = 0; j < 4; j++) acc[i][j] = 0.0f;

    gemm_mainloop2<4>(g_ht + (size_t)(by * 128) * HIDDEN,
                      W + (size_t)cb * HIDDEN, HIDDEN, acc);

    // RoPE in registers: pair (nt, nt+4) holds head-dims (d, d+32)
    if (rope) {
        float invf[8];
#pragma unroll
        for (int ntp = 0; ntp < 4; ntp++)
#pragma unroll
            for (int j = 0; j < 2; j++)
                invf[ntp * 2 + j] =
                    powf(10000.0f, -((float)(2 * (ntp * 8 + (q << 1) + j)) / 64.0f));
#pragma unroll
        for (int mt = 0; mt < 2; mt++) {
#pragma unroll
            for (int rh = 0; rh < 2; rh++) {
                const int m = by * 128 + wm * 32 + mt * 16 + g + rh * 8;
                const float s = (float)(m & (SEQ - 1));
#pragma unroll
                for (int ntp = 0; ntp < 4; ntp++) {
#pragma unroll
                    for (int j = 0; j < 2; j++) {
                        float c, si;
                        sincosf(s * invf[ntp * 2 + j], &si, &c);
                        const float x1 = acc[mt * 8 + ntp][rh * 2 + j];
                        const float x2 = acc[mt * 8 + ntp + 4][rh * 2 + j];
                        acc[mt * 8 + ntp][rh * 2 + j]     = x1 * c - x2 * si;
                        acc[mt * 8 + ntp + 4][rh * 2 + j] = x2 * c + x1 * si;
                    }
                }
            }
        }
    }

    // Scatter store to [b, h, s, d], tf32-rounded (+pre-scale for Q)
#pragma unroll
    for (int mt = 0; mt < 2; mt++) {
        const int row = by * 128 + wm * 32 + mt * 16 + g;
#pragma unroll
        for (int nt = 0; nt < 8; nt++) {
            const int col = cb + wn * 64 + nt * 8 + (q << 1);
            const int hh = col / HD, dd = col & (HD - 1);
#pragma unroll
            for (int rh = 0; rh < 2; rh++) {
                const int m = row + rh * 8;
                const int bb = m >> 11, ss = m & (SEQ - 1);
                float* p = Out + (((size_t)bb * heads + hh) * SEQ + ss) * HD + dd;
                p[0] = tf32r(acc[mt * 8 + nt][rh * 2]     * oscale);
                p[1] = tf32r(acc[mt * 8 + nt][rh * 2 + 1] * oscale);
            }
        }
    }
}

// ---------------------------------------------------------------------------
// Output projection: WARPS_M=2 (warp tile 64x32)
// ---------------------------------------------------------------------------
__global__ __launch_bounds__(256, 2)
void gemm_o(float* __restrict__ C)
{
    const int bx = blockIdx.x, by = blockIdx.y;
    const int tid = threadIdx.x;
    const int lane = tid & 31, warp = tid >> 5;
    const int wm = warp % 2, wn = warp / 2;
    const int q = lane & 3, g = lane >> 2;

    float acc[16][4];
#pragma unroll
    for (int i = 0; i < 16; i++)
#pragma unroll
        for (int j = 0; j < 4; j++) acc[i][j] = 0.0f;

    gemm_mainloop2<2>(g_attn + (size_t)(by * 128) * HIDDEN,
                      g_wot + (size_t)(bx * 128) * HIDDEN, HIDDEN, acc);

#pragma unroll
    for (int mt = 0; mt < 4; mt++) {
        const int row = by * 128 + wm * 64 + mt * 16 + g;
#pragma unroll
        for (int nt = 0; nt < 4; nt++) {
            const int col = bx * 128 + wn * 32 + nt * 8 + (q << 1);
            *(float2*)(C + (size_t)row * HIDDEN + col) =
                make_float2(acc[mt * 4 + nt][0], acc[mt * 4 + nt][1]);
            *(float2*)(C + (size_t)(row + 8) * HIDDEN + col) =
                make_float2(acc[mt * 4 + nt][2], acc[mt * 4 + nt][3]);
        }
    }
}

// ---------------------------------------------------------------------------
// Flash attention, tf32 mma.sync, causal. 64-row Q tiles, 4 warps, occ 3.
// Inputs pre-rounded & Q pre-scaled. cp.async K/V alternating pipeline.
// K fragments via paired ldsm4; P via ldsm4; V scalar. Ps aliases Qs.
// ---------------------------------------------------------------------------
#define QSTR 68
#define VSTR 72
#define FLASH_SMEM ((64 * QSTR * 2 + 64 * VSTR) * 4)

__global__ __launch_bounds__(128, 3)
void flash_tf32(const float* __restrict__ Q, const float* __restrict__ K,
                const float* __restrict__ V, float* __restrict__ O)
{
    extern __shared__ float sm[];
    float* Qs = sm;
    float* Ks = Qs + 64 * QSTR;
    float* Vs = Ks + 64 * QSTR;
    float* Ps = Qs;

    const int qb   = blockIdx.x;
    const int h    = blockIdx.y;
    const int b    = blockIdx.z;
    const int tid  = threadIdx.x;
    const int lane = tid & 31;
    const int warp = tid >> 5;
    const int q    = lane & 3;
    const int g    = lane >> 2;

    const float* Qg = Q + (((size_t)b * NH + h) * SEQ + qb * 64) * HD;
    const float* Kg = K + ((size_t)b * NKV + h / NREP) * SEQ * HD;
    const float* Vg = V + ((size_t)b * NKV + h / NREP) * SEQ * HD;

    const uint32_t sKs = (uint32_t)__cvta_generic_to_shared(Ks);
    const uint32_t sVs = (uint32_t)__cvta_generic_to_shared(Vs);
    const uint32_t sPs = (uint32_t)__cvta_generic_to_shared(Ps);

    auto issue_k = [&](int kt) {
#pragma unroll
        for (int i = 0; i < 8; i++) {
            const int f = tid + 128 * i;
            const int r = f >> 4, c4 = (f & 15) << 2;
            const uint32_t d = sKs + (uint32_t)((r * QSTR + c4) * 4);
            const float* s = Kg + (size_t)kt * 64 * HD + f * 4;
            asm volatile("cp.async.cg.shared.global [%0], [%1], 16;" :: "r"(d), "l"(s));
        }
        asm volatile("cp.async.commit_group;");
    };
    auto issue_v = [&](int kt) {
#pragma unroll
        for (int i = 0; i < 8; i++) {
            const int f = tid + 128 * i;
            const int r = f >> 4, c4 = (f & 15) << 2;
            const uint32_t d = sVs + (uint32_t)((r * VSTR + c4) * 4);
            const float* s = Vg + (size_t)kt * 64 * HD + f * 4;
            asm volatile("cp.async.cg.shared.global [%0], [%1], 16;" :: "r"(d), "l"(s));
        }
        asm volatile("cp.async.commit_group;");
    };

    issue_k(0);
    issue_v(0);

#pragma unroll
    for (int i = 0; i < 8; i++) {
        const int f = tid + 128 * i;
        const int r = f >> 4, c4 = (f & 15) << 2;
        *(float4*)&Qs[r * QSTR + c4] = *(const float4*)&Qg[r * HD + c4];
    }
    __syncthreads();

    const int rA = warp * 16 + g;

    unsigned qf[8][4];
#pragma unroll
    for (int ks = 0; ks < 8; ks++) {
        const int k0 = ks * 8;
        qf[ks][0] = F2U(Qs[rA * QSTR + k0 + q]);
        qf[ks][1] = F2U(Qs[(rA + 8) * QSTR + k0 + q]);
        qf[ks][2] = F2U(Qs[rA * QSTR + k0 + 4 + q]);
        qf[ks][3] = F2U(Qs[(rA + 8) * QSTR + k0 + 4 + q]);
    }

    // ldmatrix bases
    const int arow = ((lane >> 3) & 1) * 8 + (lane & 7);
    const int acol = (lane >> 4) * 4;
    const uint32_t pbase = sPs + (uint32_t)(((warp * 16 + arow) * QSTR + acol) * 4);
    // K-fragment x4: mat0/1 = key rows 0-7 (k0/k4), mat2/3 = key rows 8-15
    const int krow = (lane & 7) + ((lane >> 4) & 1) * 8;
    const int kcol = ((lane >> 3) & 1) * 4;
    const uint32_t kf4 = sKs + (uint32_t)((krow * QSTR + kcol) * 4);

    float m_i[2], l_i[2], o_acc[8][4];
#pragma unroll
    for (int rh = 0; rh < 2; rh++) { m_i[rh] = -INFINITY; l_i[rh] = 0.0f; }
#pragma unroll
    for (int nt = 0; nt < 8; nt++)
#pragma unroll
        for (int j = 0; j < 4; j++) o_acc[nt][j] = 0.0f;

    for (int kt = 0; kt <= qb; kt++) {
        asm volatile("cp.async.wait_group 1;");
        __syncthreads();

        float s_acc[8][4];
#pragma unroll
        for (int nt = 0; nt < 8; nt++)
#pragma unroll
            for (int j = 0; j < 4; j++) s_acc[nt][j] = 0.0f;

#pragma unroll
        for (int ks = 0; ks < 8; ks++) {
#pragma unroll
            for (int ntp = 0; ntp < 4; ntp++) {
                unsigned b0, b1, b2, b3;
                ldsm4(b0, b1, b2, b3, kf4 + (uint32_t)((ntp * 16 * QSTR + ks * 8) * 4));
                mma8(s_acc[2 * ntp],     qf[ks][0], qf[ks][1], qf[ks][2], qf[ks][3], b0, b1);
                mma8(s_acc[2 * ntp + 1], qf[ks][0], qf[ks][1], qf[ks][2], qf[ks][3], b2, b3);
            }
        }

        const bool diag = (kt == qb);

#pragma unroll
        for (int rh = 0; rh < 2; rh++) {
            const int rg = qb * 64 + rA + rh * 8;
            float mx = -INFINITY;
#pragma unroll
            for (int nt = 0; nt < 8; nt++) {
#pragma unroll
                for (int j = 0; j < 2; j++) {
                    float sv = s_acc[nt][rh * 2 + j];
                    if (diag) {
                        int cg = kt * 64 + nt * 8 + (q << 1) + j;
                        if (cg > rg) sv = -INFINITY;
                    }
                    s_acc[nt][rh * 2 + j] = sv;
                    mx = fmaxf(mx, sv);
                }
            }
            mx = fmaxf(mx, __shfl_xor_sync(0xffffffffu, mx, 1));
            mx = fmaxf(mx, __shfl_xor_sync(0xffffffffu, mx, 2));

            const float mnew = fmaxf(m_i[rh], mx);
            const float sc = __expf(m_i[rh] - mnew);
            m_i[rh] = mnew;

            float rs = 0.0f;
#pragma unroll
            for (int nt = 0; nt < 8; nt++) {
#pragma unroll
                for (int j = 0; j < 2; j++) {
                    float p = __expf(s_acc[nt][rh * 2 + j] - mnew);
                    s_acc[nt][rh * 2 + j] = p;
                    rs += p;
                }
            }
            rs += __shfl_xor_sync(0xffffffffu, rs, 1);
            rs += __shfl_xor_sync(0xffffffffu, rs, 2);

            l_i[rh] = l_i[rh] * sc + rs;
#pragma unroll
            for (int nt = 0; nt < 8; nt++) {
                o_acc[nt][rh * 2]     *= sc;
                o_acc[nt][rh * 2 + 1] *= sc;
            }
        }

#pragma unroll
        for (int nt = 0; nt < 8; nt++) {
            const int c = nt * 8 + (q << 1);
            Ps[rA * QSTR + c]           = tf32r(s_acc[nt][0]);
            Ps[rA * QSTR + c + 1]       = tf32r(s_acc[nt][1]);
            Ps[(rA + 8) * QSTR + c]     = tf32r(s_acc[nt][2]);
            Ps[(rA + 8) * QSTR + c + 1] = tf32r(s_acc[nt][3]);
        }
        __syncwarp();

        asm volatile("cp.async.wait_group 0;");
        __syncthreads();
        if (kt < qb) issue_k(kt + 1);

#pragma unroll
        for (int ks = 0; ks < 8; ks++) {
            const int k0 = ks * 8;
            unsigned a0, a1, a2, a3;
            ldsm4(a0, a1, a2, a3, pbase + (uint32_t)(k0 * 4));
#pragma unroll
            for (int nt = 0; nt < 8; nt++) {
                const int n = nt * 8 + g;
                const unsigned b0 = F2U(Vs[(k0 + q) * VSTR + n]);
                const unsigned b1 = F2U(Vs[(k0 + 4 + q) * VSTR + n]);
                mma8(o_acc[nt], a0, a1, a2, a3, b0, b1);
            }
        }
        __syncthreads();
        if (kt < qb) issue_v(kt + 1);
    }

    const float inv0 = 1.0f / l_i[0];
    const float inv1 = 1.0f / l_i[1];
#pragma unroll
    for (int nt = 0; nt < 8; nt++) {
        const int c = nt * 8 + (q << 1);
        const int r0 = qb * 64 + rA;
        float* p0 = O + ((size_t)b * SEQ + r0) * (NH * HD) + h * HD + c;
        p0[0] = tf32r(o_acc[nt][0] * inv0);
        p0[1] = tf32r(o_acc[nt][1] * inv0);
        float* p1 = O + ((size_t)b * SEQ + r0 + 8) * (NH * HD) + h * HD + c;
        p1[0] = tf32r(o_acc[nt][2] * inv1);
        p1[1] = tf32r(o_acc[nt][3] * inv1);
    }
}

// ---------------------------------------------------------------------------
// kernel_launch
// ---------------------------------------------------------------------------
extern "C" void kernel_launch(void* const* d_in, const int* in_sizes, int n_in,
                              void* d_out, int out_size)
{
    const float* hidden = (const float*)d_in[0];
    const float* wq = (const float*)d_in[1];
    const float* wk = (const float*)d_in[2];
    const float* wv = (const float*)d_in[3];
    const float* wo = (const float*)d_in[4];
    float* out = (float*)d_out;

    float *pq, *pk, *pv, *pattn, *pht, *pwqt, *pwkt, *pwvt, *pwot;
    cudaGetSymbolAddress((void**)&pq, g_q);
    cudaGetSymbolAddress((void**)&pk, g_k);
    cudaGetSymbolAddress((void**)&pv, g_v);
    cudaGetSymbolAddress((void**)&pattn, g_attn);
    cudaGetSymbolAddress((void**)&pht, g_ht);
    cudaGetSymbolAddress((void**)&pwqt, g_wqt);
    cudaGetSymbolAddress((void**)&pwkt, g_wkt);
    cudaGetSymbolAddress((void**)&pwvt, g_wvt);
    cudaGetSymbolAddress((void**)&pwot, g_wot);

    const int M = BSZ * SEQ;   // 4096

    cudaFuncSetAttribute(qkv_gemm, cudaFuncAttributeMaxDynamicSharedMemorySize, GEMM_SMEM);
    cudaFuncSetAttribute(gemm_o, cudaFuncAttributeMaxDynamicSharedMemorySize, GEMM_SMEM);
    cudaFuncSetAttribute(flash_tf32, cudaFuncAttributeMaxDynamicSharedMemorySize, FLASH_SMEM);

    // 1) round hidden; transpose+round weights to [N,K]
    const int nh4 = BSZ * SEQ * HIDDEN / 4;
    round_tf32<<<(nh4 + 255) / 256, 256>>>(hidden, pht, nh4);
    transpose_tf32<<<dim3((NH * HD) / 32, HIDDEN / 32), dim3(32, 8)>>>(wq, pwqt, HIDDEN, NH * HD);
    transpose_tf32<<<dim3((NKV * HD) / 32, HIDDEN / 32), dim3(32, 8)>>>(wk, pwkt, HIDDEN, NKV * HD);
    transpose_tf32<<<dim3((NKV * HD) / 32, HIDDEN / 32), dim3(32, 8)>>>(wv, pwvt, HIDDEN, NKV * HD);
    transpose_tf32<<<dim3(HIDDEN / 32, (NH * HD) / 32), dim3(32, 8)>>>(wo, pwot, NH * HD, HIDDEN);

    // 2) fused QKV projection + RoPE (24 N-tiles: 16 Q, 4 K, 4 V)
    qkv_gemm<<<dim3(24, M / 128), dim3(256), GEMM_SMEM>>>();

    // 3) flash attention
    flash_tf32<<<dim3(SEQ / 64, NH, BSZ), dim3(128), FLASH_SMEM>>>(pq, pk, pv, pattn);

    // 4) output projection
    gemm_o<<<dim3(HIDDEN / 128, M / 128), dim3(256), GEMM_SMEM>>>(out);
}

// round 8
// speedup vs baseline: 4.6662x; 1.1367x over previous
#include <cuda_runtime.h>
#include <math.h>
#include <stdint.h>

#define BSZ 2
#define SEQ 2048
#define HIDDEN 2048
#define NH 32
#define NKV 8
#define HD 64
#define NREP 4

// Scratch (static device arrays — no allocation).
__device__ float g_q[BSZ * NH * SEQ * HD];      // [b, h, s, d] tf32-rounded, pre-scaled 1/8
__device__ float g_k[BSZ * NKV * SEQ * HD];     // [b, kvh, s, d] tf32-rounded
__device__ float g_v[BSZ * NKV * SEQ * HD];     // [b, kvh, s, d] tf32-rounded
__device__ float g_attn[BSZ * SEQ * NH * HD];   // [b, s, h*d] tf32-rounded

__device__ float g_ht[BSZ * SEQ * HIDDEN];      // tf32-rounded hidden
__device__ float g_wqt[NH * HD * HIDDEN];       // [N,K] k-major, tf32-rounded
__device__ float g_wkt[NKV * HD * HIDDEN];
__device__ float g_wvt[NKV * HD * HIDDEN];
__device__ float g_wot[HIDDEN * NH * HD];       // [N=2048, K=2048]

// ---------------------------------------------------------------------------
// Helpers
// ---------------------------------------------------------------------------
__device__ __forceinline__ float tf32r(float x) {
    unsigned u;
    asm("cvt.rna.tf32.f32 %0, %1;" : "=r"(u) : "f"(x));
    return __uint_as_float(u);
}
#define F2U __float_as_uint

__device__ __forceinline__ void mma8(float c[4],
                                     unsigned a0, unsigned a1, unsigned a2, unsigned a3,
                                     unsigned b0, unsigned b1) {
    asm volatile(
        "mma.sync.aligned.m16n8k8.row.col.f32.tf32.tf32.f32 "
        "{%0,%1,%2,%3}, {%4,%5,%6,%7}, {%8,%9}, {%0,%1,%2,%3};\n"
        : "+f"(c[0]), "+f"(c[1]), "+f"(c[2]), "+f"(c[3])
        : "r"(a0), "r"(a1), "r"(a2), "r"(a3), "r"(b0), "r"(b1));
}
__device__ __forceinline__ void ldsm4(unsigned& r0, unsigned& r1,
                                      unsigned& r2, unsigned& r3, uint32_t addr) {
    asm volatile("ldmatrix.sync.aligned.m8n8.x4.shared.b16 {%0,%1,%2,%3}, [%4];"
                 : "=r"(r0), "=r"(r1), "=r"(r2), "=r"(r3) : "r"(addr));
}

// ---------------------------------------------------------------------------
// Prologue kernels: elementwise round; tiled transpose+round
// ---------------------------------------------------------------------------
__global__ void round_tf32(const float* __restrict__ src, float* __restrict__ dst, int n4)
{
    int i = blockIdx.x * blockDim.x + threadIdx.x;
    if (i >= n4) return;
    float4 v = ((const float4*)src)[i];
    v.x = tf32r(v.x); v.y = tf32r(v.y); v.z = tf32r(v.z); v.w = tf32r(v.w);
    ((float4*)dst)[i] = v;
}

// dst[n*Kd + k] = tf32r(src[k*Nd + n])
__global__ void transpose_tf32(const float* __restrict__ src, float* __restrict__ dst,
                               int Kd, int Nd)
{
    __shared__ float t[32][33];
    const int n0 = blockIdx.x * 32, k0 = blockIdx.y * 32;
    const int tx = threadIdx.x, ty = threadIdx.y;
#pragma unroll
    for (int i = 0; i < 4; i++)
        t[ty + i * 8][tx] = src[(size_t)(k0 + ty + i * 8) * Nd + n0 + tx];
    __syncthreads();
#pragma unroll
    for (int i = 0; i < 4; i++)
        dst[(size_t)(n0 + ty + i * 8) * Kd + k0 + tx] = tf32r(t[tx][ty + i * 8]);
}

// ---------------------------------------------------------------------------
// GEMM mainloop v3: 128x128 tile, BK=32, 256 thr (8 warps), 3-stage cp.async,
// XOR-swizzled smem (exact 128B rows, no padding). A [128,K] k-major,
// B [128 n-rows, K] k-major. Both fragments via ldmatrix (conflict-free).
// Stage = 128 rows x 128B = 16KB per matrix; 3*(16+16)KB = 96KB -> 2 CTA/SM.
// Prefetch distance: issue kc+2 at end of iter kc (hazard-free: barrier at
// top of iter kc guarantees stage (kc-1)%3 == (kc+2)%3 is drained).
// ---------------------------------------------------------------------------
#define STAGE_B 16384u                     // bytes per (A or B) stage
#define GEMM_SMEM (6 * 16384)              // 98304 bytes

template<int WARPS_M>
__device__ __forceinline__ void gemm_mainloop3(
    const float* __restrict__ Ag, const float* __restrict__ Bg,
    int K, float (*acc)[4])
{
    extern __shared__ float smem[];
    constexpr int MT = 8 / WARPS_M;        // m-tiles (16 rows each)
    constexpr int NT = 2 * WARPS_M;        // n-tiles (8 cols each)
    constexpr int NPAIR = NT / 2;

    const int tid  = threadIdx.x;
    const int lane = tid & 31;
    const int warp = tid >> 5;
    const int wm   = warp % WARPS_M;
    const int wn   = warp / WARPS_M;

    const uint32_t sA = (uint32_t)__cvta_generic_to_shared(smem);
    const uint32_t sB = sA + 3 * STAGE_B;

    // cp.async per-thread constants: row group (tid>>3), 16B chunk (tid&7)
    const int lrow = tid >> 3;             // 0..31 (rows lrow + 32*i)
    const int lj   = tid & 7;              // 16B chunk within 128B row
    const uint32_t wsw = (uint32_t)((lj ^ (lrow & 7)) << 4);   // swizzled byte off

    // A-fragment per-lane constants
    const int frow = ((lane >> 3) & 1) * 8 + (lane & 7);
    const int fjb  = lane >> 4;            // chunk bit (k0 vs k0+4)
    const int axr  = frow & 7;
    const uint32_t arowb = (uint32_t)((wm * MT * 16 + frow) * 128);
    // B-fragment per-lane constants
    const int brow = (lane & 7) + ((lane >> 4) & 1) * 8;
    const int bjb  = (lane >> 3) & 1;
    const int bxr  = brow & 7;
    const uint32_t browb = (uint32_t)((wn * NT * 8 + brow) * 128);

#define ISSUE(kc, st) do {                                                           \
    _Pragma("unroll")                                                                \
    for (int i = 0; i < 4; i++) {                                                    \
        const int r = lrow + 32 * i;                                                 \
        const float* sa = Ag + (size_t)r * K + (kc) * 32 + lj * 4;                   \
        const uint32_t da = sA + (uint32_t)(st) * STAGE_B + (uint32_t)(r * 128) + wsw; \
        asm volatile("cp.async.cg.shared.global [%0], [%1], 16;" :: "r"(da), "l"(sa)); \
    }                                                                                \
    _Pragma("unroll")                                                                \
    for (int i = 0; i < 4; i++) {                                                    \
        const int r = lrow + 32 * i;                                                 \
        const float* sb = Bg + (size_t)r * K + (kc) * 32 + lj * 4;                   \
        const uint32_t db = sB + (uint32_t)(st) * STAGE_B + (uint32_t)(r * 128) + wsw; \
        asm volatile("cp.async.cg.shared.global [%0], [%1], 16;" :: "r"(db), "l"(sb)); \
    }                                                                                \
    asm volatile("cp.async.commit_group;");                                          \
} while (0)

    const int nkc = K >> 5;                // 64
    ISSUE(0, 0);
    ISSUE(1, 1);

    for (int kc = 0; kc < nkc; kc++) {
        if (kc < nkc - 1) asm volatile("cp.async.wait_group 1;");
        else              asm volatile("cp.async.wait_group 0;");
        __syncthreads();

        const int st = kc % 3;
        const uint32_t aS = sA + (uint32_t)st * STAGE_B;
        const uint32_t bS = sB + (uint32_t)st * STAGE_B;

#pragma unroll
        for (int ks = 0; ks < 4; ks++) {
            unsigned a[MT][4];
#pragma unroll
            for (int mt = 0; mt < MT; mt++)
                ldsm4(a[mt][0], a[mt][1], a[mt][2], a[mt][3],
                      aS + arowb + (uint32_t)(mt * 2048)
                         + (uint32_t)((((2 * ks + fjb) ^ axr)) << 4));
#pragma unroll
            for (int ntp = 0; ntp < NPAIR; ntp++) {
                unsigned b0, b1, b2, b3;
                ldsm4(b0, b1, b2, b3,
                      bS + browb + (uint32_t)(ntp * 2048)
                         + (uint32_t)((((2 * ks + bjb) ^ bxr)) << 4));
#pragma unroll
                for (int mt = 0; mt < MT; mt++) {
                    mma8(acc[mt * NT + 2 * ntp],     a[mt][0], a[mt][1], a[mt][2], a[mt][3], b0, b1);
                    mma8(acc[mt * NT + 2 * ntp + 1], a[mt][0], a[mt][1], a[mt][2], a[mt][3], b2, b3);
                }
            }
        }
        if (kc + 2 < nkc) ISSUE(kc + 2, (kc + 2) % 3);
    }
#undef ISSUE
}

// ---------------------------------------------------------------------------
// Fused QKV projection + RoPE epilogue. WARPS_M=4 (warp tile 32x64; RoPE
// pairs (d, d+32) stay in-warp as nt, nt+4).
// grid.x = 24: bx<16 -> Q, bx<20 -> K, else V.
// ---------------------------------------------------------------------------
__global__ __launch_bounds__(256, 2)
void qkv_gemm()
{
    const int bx = blockIdx.x, by = blockIdx.y;
    const int tid = threadIdx.x;
    const int lane = tid & 31, warp = tid >> 5;
    const int wm = warp % 4, wn = warp / 4;
    const int q = lane & 3, g = lane >> 2;

    const float* W;
    float* Out;
    int cb, heads;
    bool rope;
    float oscale;
    if (bx < 16)      { W = g_wqt; Out = g_q; cb = bx * 128;        heads = NH;  rope = true;  oscale = 0.125f; }
    else if (bx < 20) { W = g_wkt; Out = g_k; cb = (bx - 16) * 128; heads = NKV; rope = true;  oscale = 1.0f; }
    else              { W = g_wvt; Out = g_v; cb = (bx - 20) * 128; heads = NKV; rope = false; oscale = 1.0f; }

    float acc[16][4];
#pragma unroll
    for (int i = 0; i < 16; i++)
#pragma unroll
        for (int j = 0; j < 4; j++) acc[i][j] = 0.0f;

    gemm_mainloop3<4>(g_ht + (size_t)(by * 128) * HIDDEN,
                      W + (size_t)cb * HIDDEN, HIDDEN, acc);

    // RoPE in registers: pair (nt, nt+4) holds head-dims (d, d+32)
    if (rope) {
        float invf[8];
#pragma unroll
        for (int ntp = 0; ntp < 4; ntp++)
#pragma unroll
            for (int j = 0; j < 2; j++)
                invf[ntp * 2 + j] =
                    powf(10000.0f, -((float)(2 * (ntp * 8 + (q << 1) + j)) / 64.0f));
#pragma unroll
        for (int mt = 0; mt < 2; mt++) {
#pragma unroll
            for (int rh = 0; rh < 2; rh++) {
                const int m = by * 128 + wm * 32 + mt * 16 + g + rh * 8;
                const float s = (float)(m & (SEQ - 1));
#pragma unroll
                for (int ntp = 0; ntp < 4; ntp++) {
#pragma unroll
                    for (int j = 0; j < 2; j++) {
                        float c, si;
                        sincosf(s * invf[ntp * 2 + j], &si, &c);
                        const float x1 = acc[mt * 8 + ntp][rh * 2 + j];
                        const float x2 = acc[mt * 8 + ntp + 4][rh * 2 + j];
                        acc[mt * 8 + ntp][rh * 2 + j]     = x1 * c - x2 * si;
                        acc[mt * 8 + ntp + 4][rh * 2 + j] = x2 * c + x1 * si;
                    }
                }
            }
        }
    }

    // Scatter store to [b, h, s, d], tf32-rounded (+pre-scale for Q)
#pragma unroll
    for (int mt = 0; mt < 2; mt++) {
        const int row = by * 128 + wm * 32 + mt * 16 + g;
#pragma unroll
        for (int nt = 0; nt < 8; nt++) {
            const int col = cb + wn * 64 + nt * 8 + (q << 1);
            const int hh = col / HD, dd = col & (HD - 1);
#pragma unroll
            for (int rh = 0; rh < 2; rh++) {
                const int m = row + rh * 8;
                const int bb = m >> 11, ss = m & (SEQ - 1);
                float* p = Out + (((size_t)bb * heads + hh) * SEQ + ss) * HD + dd;
                p[0] = tf32r(acc[mt * 8 + nt][rh * 2]     * oscale);
                p[1] = tf32r(acc[mt * 8 + nt][rh * 2 + 1] * oscale);
            }
        }
    }
}

// ---------------------------------------------------------------------------
// Output projection: WARPS_M=2 (warp tile 64x32)
// ---------------------------------------------------------------------------
__global__ __launch_bounds__(256, 2)
void gemm_o(float* __restrict__ C)
{
    const int bx = blockIdx.x, by = blockIdx.y;
    const int tid = threadIdx.x;
    const int lane = tid & 31, warp = tid >> 5;
    const int wm = warp % 2, wn = warp / 2;
    const int q = lane & 3, g = lane >> 2;

    float acc[16][4];
#pragma unroll
    for (int i = 0; i < 16; i++)
#pragma unroll
        for (int j = 0; j < 4; j++) acc[i][j] = 0.0f;

    gemm_mainloop3<2>(g_attn + (size_t)(by * 128) * HIDDEN,
                      g_wot + (size_t)(bx * 128) * HIDDEN, HIDDEN, acc);

#pragma unroll
    for (int mt = 0; mt < 4; mt++) {
        const int row = by * 128 + wm * 64 + mt * 16 + g;
#pragma unroll
        for (int nt = 0; nt < 4; nt++) {
            const int col = bx * 128 + wn * 32 + nt * 8 + (q << 1);
            *(float2*)(C + (size_t)row * HIDDEN + col) =
                make_float2(acc[mt * 4 + nt][0], acc[mt * 4 + nt][1]);
            *(float2*)(C + (size_t)(row + 8) * HIDDEN + col) =
                make_float2(acc[mt * 4 + nt][2], acc[mt * 4 + nt][3]);
        }
    }
}

// ---------------------------------------------------------------------------
// Flash attention, tf32 mma.sync, causal. 64-row Q tiles, 4 warps, occ 3.
// Inputs pre-rounded & Q pre-scaled. cp.async K/V alternating pipeline.
// K fragments via paired ldsm4; P via ldsm4; V scalar. Ps aliases Qs.
// ---------------------------------------------------------------------------
#define QSTR 68
#define VSTR 72
#define FLASH_SMEM ((64 * QSTR * 2 + 64 * VSTR) * 4)

__global__ __launch_bounds__(128, 3)
void flash_tf32(const float* __restrict__ Q, const float* __restrict__ K,
                const float* __restrict__ V, float* __restrict__ O)
{
    extern __shared__ float sm[];
    float* Qs = sm;
    float* Ks = Qs + 64 * QSTR;
    float* Vs = Ks + 64 * QSTR;
    float* Ps = Qs;

    const int qb   = blockIdx.x;
    const int h    = blockIdx.y;
    const int b    = blockIdx.z;
    const int tid  = threadIdx.x;
    const int lane = tid & 31;
    const int warp = tid >> 5;
    const int q    = lane & 3;
    const int g    = lane >> 2;

    const float* Qg = Q + (((size_t)b * NH + h) * SEQ + qb * 64) * HD;
    const float* Kg = K + ((size_t)b * NKV + h / NREP) * SEQ * HD;
    const float* Vg = V + ((size_t)b * NKV + h / NREP) * SEQ * HD;

    const uint32_t sKs = (uint32_t)__cvta_generic_to_shared(Ks);
    const uint32_t sVs = (uint32_t)__cvta_generic_to_shared(Vs);
    const uint32_t sPs = (uint32_t)__cvta_generic_to_shared(Ps);

    auto issue_k = [&](int kt) {
#pragma unroll
        for (int i = 0; i < 8; i++) {
            const int f = tid + 128 * i;
            const int r = f >> 4, c4 = (f & 15) << 2;
            const uint32_t d = sKs + (uint32_t)((r * QSTR + c4) * 4);
            const float* s = Kg + (size_t)kt * 64 * HD + f * 4;
            asm volatile("cp.async.cg.shared.global [%0], [%1], 16;" :: "r"(d), "l"(s));
        }
        asm volatile("cp.async.commit_group;");
    };
    auto issue_v = [&](int kt) {
#pragma unroll
        for (int i = 0; i < 8; i++) {
            const int f = tid + 128 * i;
            const int r = f >> 4, c4 = (f & 15) << 2;
            const uint32_t d = sVs + (uint32_t)((r * VSTR + c4) * 4);
            const float* s = Vg + (size_t)kt * 64 * HD + f * 4;
            asm volatile("cp.async.cg.shared.global [%0], [%1], 16;" :: "r"(d), "l"(s));
        }
        asm volatile("cp.async.commit_group;");
    };

    issue_k(0);
    issue_v(0);

#pragma unroll
    for (int i = 0; i < 8; i++) {
        const int f = tid + 128 * i;
        const int r = f >> 4, c4 = (f & 15) << 2;
        *(float4*)&Qs[r * QSTR + c4] = *(const float4*)&Qg[r * HD + c4];
    }
    __syncthreads();

    const int rA = warp * 16 + g;

    unsigned qf[8][4];
#pragma unroll
    for (int ks = 0; ks < 8; ks++) {
        const int k0 = ks * 8;
        qf[ks][0] = F2U(Qs[rA * QSTR + k0 + q]);
        qf[ks][1] = F2U(Qs[(rA + 8) * QSTR + k0 + q]);
        qf[ks][2] = F2U(Qs[rA * QSTR + k0 + 4 + q]);
        qf[ks][3] = F2U(Qs[(rA + 8) * QSTR + k0 + 4 + q]);
    }

    // ldmatrix bases
    const int arow = ((lane >> 3) & 1) * 8 + (lane & 7);
    const int acol = (lane >> 4) * 4;
    const uint32_t pbase = sPs + (uint32_t)(((warp * 16 + arow) * QSTR + acol) * 4);
    const int krow = (lane & 7) + ((lane >> 4) & 1) * 8;
    const int kcol = ((lane >> 3) & 1) * 4;
    const uint32_t kf4 = sKs + (uint32_t)((krow * QSTR + kcol) * 4);

    float m_i[2], l_i[2], o_acc[8][4];
#pragma unroll
    for (int rh = 0; rh < 2; rh++) { m_i[rh] = -INFINITY; l_i[rh] = 0.0f; }
#pragma unroll
    for (int nt = 0; nt < 8; nt++)
#pragma unroll
        for (int j = 0; j < 4; j++) o_acc[nt][j] = 0.0f;

    for (int kt = 0; kt <= qb; kt++) {
        asm volatile("cp.async.wait_group 1;");
        __syncthreads();

        float s_acc[8][4];
#pragma unroll
        for (int nt = 0; nt < 8; nt++)
#pragma unroll
            for (int j = 0; j < 4; j++) s_acc[nt][j] = 0.0f;

#pragma unroll
        for (int ks = 0; ks < 8; ks++) {
#pragma unroll
            for (int ntp = 0; ntp < 4; ntp++) {
                unsigned b0, b1, b2, b3;
                ldsm4(b0, b1, b2, b3, kf4 + (uint32_t)((ntp * 16 * QSTR + ks * 8) * 4));
                mma8(s_acc[2 * ntp],     qf[ks][0], qf[ks][1], qf[ks][2], qf[ks][3], b0, b1);
                mma8(s_acc[2 * ntp + 1], qf[ks][0], qf[ks][1], qf[ks][2], qf[ks][3], b2, b3);
            }
        }

        const bool diag = (kt == qb);

#pragma unroll
        for (int rh = 0; rh < 2; rh++) {
            const int rg = qb * 64 + rA + rh * 8;
            float mx = -INFINITY;
#pragma unroll
            for (int nt = 0; nt < 8; nt++) {
#pragma unroll
                for (int j = 0; j < 2; j++) {
                    float sv = s_acc[nt][rh * 2 + j];
                    if (diag) {
                        int cg = kt * 64 + nt * 8 + (q << 1) + j;
                        if (cg > rg) sv = -INFINITY;
                    }
                    s_acc[nt][rh * 2 + j] = sv;
                    mx = fmaxf(mx, sv);
                }
            }
            mx = fmaxf(mx, __shfl_xor_sync(0xffffffffu, mx, 1));
            mx = fmaxf(mx, __shfl_xor_sync(0xffffffffu, mx, 2));

            const float mnew = fmaxf(m_i[rh], mx);
            const float sc = __expf(m_i[rh] - mnew);
            m_i[rh] = mnew;

            float rs = 0.0f;
#pragma unroll
            for (int nt = 0; nt < 8; nt++) {
#pragma unroll
                for (int j = 0; j < 2; j++) {
                    float p = __expf(s_acc[nt][rh * 2 + j] - mnew);
                    s_acc[nt][rh * 2 + j] = p;
                    rs += p;
                }
            }
            rs += __shfl_xor_sync(0xffffffffu, rs, 1);
            rs += __shfl_xor_sync(0xffffffffu, rs, 2);

            l_i[rh] = l_i[rh] * sc + rs;
#pragma unroll
            for (int nt = 0; nt < 8; nt++) {
                o_acc[nt][rh * 2]     *= sc;
                o_acc[nt][rh * 2 + 1] *= sc;
            }
        }

#pragma unroll
        for (int nt = 0; nt < 8; nt++) {
            const int c = nt * 8 + (q << 1);
            Ps[rA * QSTR + c]           = tf32r(s_acc[nt][0]);
            Ps[rA * QSTR + c + 1]       = tf32r(s_acc[nt][1]);
            Ps[(rA + 8) * QSTR + c]     = tf32r(s_acc[nt][2]);
            Ps[(rA + 8) * QSTR + c + 1] = tf32r(s_acc[nt][3]);
        }
        __syncwarp();

        asm volatile("cp.async.wait_group 0;");
        __syncthreads();
        if (kt < qb) issue_k(kt + 1);

#pragma unroll
        for (int ks = 0; ks < 8; ks++) {
            const int k0 = ks * 8;
            unsigned a0, a1, a2, a3;
            ldsm4(a0, a1, a2, a3, pbase + (uint32_t)(k0 * 4));
#pragma unroll
            for (int nt = 0; nt < 8; nt++) {
                const int n = nt * 8 + g;
                const unsigned b0 = F2U(Vs[(k0 + q) * VSTR + n]);
                const unsigned b1 = F2U(Vs[(k0 + 4 + q) * VSTR + n]);
                mma8(o_acc[nt], a0, a1, a2, a3, b0, b1);
            }
        }
        __syncthreads();
        if (kt < qb) issue_v(kt + 1);
    }

    const float inv0 = 1.0f / l_i[0];
    const float inv1 = 1.0f / l_i[1];
#pragma unroll
    for (int nt = 0; nt < 8; nt++) {
        const int c = nt * 8 + (q << 1);
        const int r0 = qb * 64 + rA;
        float* p0 = O + ((size_t)b * SEQ + r0) * (NH * HD) + h * HD + c;
        p0[0] = tf32r(o_acc[nt][0] * inv0);
        p0[1] = tf32r(o_acc[nt][1] * inv0);
        float* p1 = O + ((size_t)b * SEQ + r0 + 8) * (NH * HD) + h * HD + c;
        p1[0] = tf32r(o_acc[nt][2] * inv1);
        p1[1] = tf32r(o_acc[nt][3] * inv1);
    }
}

// ---------------------------------------------------------------------------
// kernel_launch
// ---------------------------------------------------------------------------
extern "C" void kernel_launch(void* const* d_in, const int* in_sizes, int n_in,
                              void* d_out, int out_size)
{
    const float* hidden = (const float*)d_in[0];
    const float* wq = (const float*)d_in[1];
    const float* wk = (const float*)d_in[2];
    const float* wv = (const float*)d_in[3];
    const float* wo = (const float*)d_in[4];
    float* out = (float*)d_out;

    float *pq, *pk, *pv, *pattn, *pht, *pwqt, *pwkt, *pwvt, *pwot;
    cudaGetSymbolAddress((void**)&pq, g_q);
    cudaGetSymbolAddress((void**)&pk, g_k);
    cudaGetSymbolAddress((void**)&pv, g_v);
    cudaGetSymbolAddress((void**)&pattn, g_attn);
    cudaGetSymbolAddress((void**)&pht, g_ht);
    cudaGetSymbolAddress((void**)&pwqt, g_wqt);
    cudaGetSymbolAddress((void**)&pwkt, g_wkt);
    cudaGetSymbolAddress((void**)&pwvt, g_wvt);
    cudaGetSymbolAddress((void**)&pwot, g_wot);

    const int M = BSZ * SEQ;   // 4096

    cudaFuncSetAttribute(qkv_gemm, cudaFuncAttributeMaxDynamicSharedMemorySize, GEMM_SMEM);
    cudaFuncSetAttribute(gemm_o, cudaFuncAttributeMaxDynamicSharedMemorySize, GEMM_SMEM);
    cudaFuncSetAttribute(flash_tf32, cudaFuncAttributeMaxDynamicSharedMemorySize, FLASH_SMEM);

    // 1) round hidden; transpose+round weights to [N,K]
    const int nh4 = BSZ * SEQ * HIDDEN / 4;
    round_tf32<<<(nh4 + 255) / 256, 256>>>(hidden, pht, nh4);
    transpose_tf32<<<dim3((NH * HD) / 32, HIDDEN / 32), dim3(32, 8)>>>(wq, pwqt, HIDDEN, NH * HD);
    transpose_tf32<<<dim3((NKV * HD) / 32, HIDDEN / 32), dim3(32, 8)>>>(wk, pwkt, HIDDEN, NKV * HD);
    transpose_tf32<<<dim3((NKV * HD) / 32, HIDDEN / 32), dim3(32, 8)>>>(wv, pwvt, HIDDEN, NKV * HD);
    transpose_tf32<<<dim3(HIDDEN / 32, (NH * HD) / 32), dim3(32, 8)>>>(wo, pwot, NH * HD, HIDDEN);

    // 2) fused QKV projection + RoPE (24 N-tiles: 16 Q, 4 K, 4 V)
    qkv_gemm<<<dim3(24, M / 128), dim3(256), GEMM_SMEM>>>();

    // 3) flash attention
    flash_tf32<<<dim3(SEQ / 64, NH, BSZ), dim3(128), FLASH_SMEM>>>(pq, pk, pv, pattn);

    // 4) output projection
    gemm_o<<<dim3(HIDDEN / 128, M / 128), dim3(256), GEMM_SMEM>>>(out);
}